// round 4
// baseline (speedup 1.0000x reference)
#include <cuda_runtime.h>
#include <math.h>
#include <stdint.h>

#define BATCH 16
#define HDIM  768
#define NDIM  2048
#define KC    16

// Scratch (allocation-free rule: __device__ globals)
__device__ float g_E[(size_t)BATCH * NDIM * NDIM];       // unnormalized exp(logits)
__device__ float g_Lpart[(size_t)BATCH * 8 * NDIM];      // per-mtile partial row sums
__device__ float g_L[(size_t)BATCH * NDIM];              // 1 / rowsum

__device__ __forceinline__ float tf32r(float x) {
    float y;
    asm("cvt.rna.tf32.f32 %0, %1;" : "=f"(y) : "f"(x));
    return y;
}

__device__ __forceinline__ void mma_tf32(float* c, const unsigned* a, const unsigned* b) {
    asm volatile(
        "mma.sync.aligned.m16n8k8.row.col.f32.tf32.tf32.f32 "
        "{%0,%1,%2,%3}, {%4,%5,%6,%7}, {%8,%9}, {%0,%1,%2,%3};\n"
        : "+f"(c[0]), "+f"(c[1]), "+f"(c[2]), "+f"(c[3])
        : "r"(a[0]), "r"(a[1]), "r"(a[2]), "r"(a[3]),
          "r"(b[0]), "r"(b[1]));
}

// ===========================================================================
// GEMM1: S[n][m] = sum_h Q[h][n]*(K[h][m]+PE[h][m]). CTA 128(n) x 256(m).
// 8 warps = 2(n) x 4(m), warp tile 64x64. Double-buffered k-major smem,
// KC=16. Smem (floats): Qs[2][16][136] @0, Ks[2][16][264] @4352, Lred @12800.
// Epilogue: E = exp(S*scale) -> g_E, partial row sums -> g_Lpart.
// ===========================================================================
__global__ __launch_bounds__(256, 1)
void gemm1_k(const float* __restrict__ Q, const float* __restrict__ K,
             const float* __restrict__ PE) {
    extern __shared__ float S[];
    const int b = blockIdx.z, m0 = blockIdx.x * 256, n0 = blockIdx.y * 128;
    const int tid = threadIdx.x, lane = tid & 31, w = tid >> 5;
    const int gid = lane >> 2, tig = lane & 3;
    const int wn = (w & 1) * 64;    // n offset of warp
    const int wm = (w >> 1) * 64;   // m offset of warp

    const float* Qb = Q  + (size_t)b * HDIM * NDIM;
    const float* Kb = K  + (size_t)b * HDIM * NDIM;
    const float* Pb = PE + (size_t)b * HDIM * NDIM;

    float acc[4][8][4];
#pragma unroll
    for (int i = 0; i < 4; i++)
#pragma unroll
        for (int j = 0; j < 8; j++)
#pragma unroll
            for (int r = 0; r < 4; r++) acc[i][j][r] = 0.f;

    float4 qr[2], kr[4];
    const int qrow = tid >> 5, qc = (tid & 31) * 4;   // Q tile: 16 x 128
    const int krow = tid >> 6, kc = (tid & 63) * 4;   // K tile: 16 x 256

    auto ldg = [&](int c) {
        const int h0 = c * KC;
#pragma unroll
        for (int i = 0; i < 2; i++)
            qr[i] = *(const float4*)(Qb + (size_t)(h0 + i * 8 + qrow) * NDIM + n0 + qc);
#pragma unroll
        for (int i = 0; i < 4; i++) {
            const float4 kv = *(const float4*)(Kb + (size_t)(h0 + i * 4 + krow) * NDIM + m0 + kc);
            const float4 pv = *(const float4*)(Pb + (size_t)(h0 + i * 4 + krow) * NDIM + m0 + kc);
            kr[i] = make_float4(kv.x + pv.x, kv.y + pv.y, kv.z + pv.z, kv.w + pv.w);
        }
    };
    auto sts = [&](int s) {
        float* Qs = S + s * 2176;
        float* Ks = S + 4352 + s * 4224;
#pragma unroll
        for (int i = 0; i < 2; i++)
            *(float4*)(Qs + (i * 8 + qrow) * 136 + qc) =
                make_float4(tf32r(qr[i].x), tf32r(qr[i].y), tf32r(qr[i].z), tf32r(qr[i].w));
#pragma unroll
        for (int i = 0; i < 4; i++)
            *(float4*)(Ks + (i * 4 + krow) * 264 + kc) =
                make_float4(tf32r(kr[i].x), tf32r(kr[i].y), tf32r(kr[i].z), tf32r(kr[i].w));
    };
    auto mma_chunk = [&](int s) {
        const float* Qs = S + s * 2176;
        const float* Ks = S + 4352 + s * 4224;
#pragma unroll
        for (int kk = 0; kk < KC; kk += 8) {
            unsigned a[4][4], bb[8][2];
#pragma unroll
            for (int mf = 0; mf < 4; mf++) {
                a[mf][0] = __float_as_uint(Qs[(kk + tig) * 136     + wn + mf * 16 + gid    ]);
                a[mf][1] = __float_as_uint(Qs[(kk + tig) * 136     + wn + mf * 16 + gid + 8]);
                a[mf][2] = __float_as_uint(Qs[(kk + tig + 4) * 136 + wn + mf * 16 + gid    ]);
                a[mf][3] = __float_as_uint(Qs[(kk + tig + 4) * 136 + wn + mf * 16 + gid + 8]);
            }
#pragma unroll
            for (int nn = 0; nn < 8; nn++) {
                bb[nn][0] = __float_as_uint(Ks[(kk + tig) * 264     + wm + nn * 8 + gid]);
                bb[nn][1] = __float_as_uint(Ks[(kk + tig + 4) * 264 + wm + nn * 8 + gid]);
            }
#pragma unroll
            for (int mf = 0; mf < 4; mf++)
#pragma unroll
                for (int nn = 0; nn < 8; nn++)
                    mma_tf32(acc[mf][nn], a[mf], bb[nn]);
        }
    };

    const int NC = HDIM / KC;   // 48
    ldg(0);
    sts(0);
    __syncthreads();
#pragma unroll 1
    for (int c = 0; c < NC; c++) {
        if (c + 1 < NC) ldg(c + 1);
        mma_chunk(c & 1);
        if (c + 1 < NC) sts((c + 1) & 1);
        __syncthreads();
    }

    // Epilogue
    const float scale = 0.03608439182435161f;   // 1/sqrt(768)
    float* Eb = g_E + (size_t)b * NDIM * NDIM;
    float* Lred = S + 12800;
#pragma unroll
    for (int mf = 0; mf < 4; mf++) {
        float rs0 = 0.f, rs1 = 0.f;
#pragma unroll
        for (int nn = 0; nn < 8; nn++) {
            const float e0 = __expf(acc[mf][nn][0] * scale);
            const float e1 = __expf(acc[mf][nn][1] * scale);
            const float e2 = __expf(acc[mf][nn][2] * scale);
            const float e3 = __expf(acc[mf][nn][3] * scale);
            rs0 += e0 + e1;
            rs1 += e2 + e3;
            const int row = n0 + wn + mf * 16 + gid;
            const int col = m0 + wm + nn * 8 + tig * 2;
            *(float2*)(Eb + (size_t)row * NDIM + col)       = make_float2(e0, e1);
            *(float2*)(Eb + (size_t)(row + 8) * NDIM + col) = make_float2(e2, e3);
        }
        rs0 += __shfl_xor_sync(0xffffffffu, rs0, 1);
        rs0 += __shfl_xor_sync(0xffffffffu, rs0, 2);
        rs1 += __shfl_xor_sync(0xffffffffu, rs1, 1);
        rs1 += __shfl_xor_sync(0xffffffffu, rs1, 2);
        if (tig == 0) {
            Lred[(w >> 1) * 128 + wn + mf * 16 + gid]     = rs0;
            Lred[(w >> 1) * 128 + wn + mf * 16 + gid + 8] = rs1;
        }
    }
    __syncthreads();
    if (tid < 128) {
        const float s2 = Lred[tid] + Lred[128 + tid] + Lred[256 + tid] + Lred[384 + tid];
        g_Lpart[((size_t)b * 8 + blockIdx.x) * NDIM + n0 + tid] = s2;
    }
}

// ===========================================================================
// Row-sum reduction -> reciprocal: g_L[b][n] = 1 / sum_j Lpart[b][j][n]
// ===========================================================================
__global__ void rowsum_k() {
    const int t = blockIdx.x * blockDim.x + threadIdx.x;
    const int b = t >> 11, n = t & 2047;
    float s = 0.f;
#pragma unroll
    for (int j = 0; j < 8; j++)
        s += g_Lpart[((size_t)b * 8 + j) * NDIM + n];
    g_L[(size_t)b * NDIM + n] = 1.0f / s;
}

// ===========================================================================
// GEMM2: O[h][n] = (sum_m V[h][m]*E[n][m]) * Linv[n]. CTA 128(h) x 256(n).
// 8 warps = 2(h) x 4(n), warp tile 64x64. Double-buffered [col][k] smem,
// row stride 20 floats (bank-bijective (20*gid+tig) mod 32).
// Smem (floats): Vs[2][128][20] @0, Es[2][256][20] @5120.
// ===========================================================================
__global__ __launch_bounds__(256, 1)
void gemm2_k(const float* __restrict__ V, float* __restrict__ out) {
    extern __shared__ float S[];
    const int b = blockIdx.z, n0 = blockIdx.x * 256, h0 = blockIdx.y * 128;
    const int tid = threadIdx.x, lane = tid & 31, w = tid >> 5;
    const int gid = lane >> 2, tig = lane & 3;
    const int wh = (w & 1) * 64;    // h offset
    const int wn = (w >> 1) * 64;   // n offset

    const float* Vb = V   + (size_t)b * HDIM * NDIM;
    const float* Eb = g_E + (size_t)b * NDIM * NDIM;

    float acc[4][8][4];
#pragma unroll
    for (int i = 0; i < 4; i++)
#pragma unroll
        for (int j = 0; j < 8; j++)
#pragma unroll
            for (int r = 0; r < 4; r++) acc[i][j][r] = 0.f;

    float4 vr[2], er[4];
    const int frow = tid >> 2, fc = (tid & 3) * 4;   // 4 float4 per 16-wide row

    auto ldg = [&](int c) {
        const int mb = c * KC;
#pragma unroll
        for (int i = 0; i < 2; i++)
            vr[i] = *(const float4*)(Vb + (size_t)(h0 + i * 64 + frow) * NDIM + mb + fc);
#pragma unroll
        for (int i = 0; i < 4; i++)
            er[i] = *(const float4*)(Eb + (size_t)(n0 + i * 64 + frow) * NDIM + mb + fc);
    };
    auto sts = [&](int s) {
        float* Vs = S + s * 2560;
        float* Es = S + 5120 + s * 5120;
#pragma unroll
        for (int i = 0; i < 2; i++)
            *(float4*)(Vs + (i * 64 + frow) * 20 + fc) =
                make_float4(tf32r(vr[i].x), tf32r(vr[i].y), tf32r(vr[i].z), tf32r(vr[i].w));
#pragma unroll
        for (int i = 0; i < 4; i++)
            *(float4*)(Es + (i * 64 + frow) * 20 + fc) =
                make_float4(tf32r(er[i].x), tf32r(er[i].y), tf32r(er[i].z), tf32r(er[i].w));
    };
    auto mma_chunk = [&](int s) {
        const float* Vs = S + s * 2560;
        const float* Es = S + 5120 + s * 5120;
#pragma unroll
        for (int kk = 0; kk < KC; kk += 8) {
            unsigned a[4][4], bb[8][2];
#pragma unroll
            for (int mf = 0; mf < 4; mf++) {
                a[mf][0] = __float_as_uint(Vs[(wh + mf * 16 + gid) * 20     + kk + tig    ]);
                a[mf][1] = __float_as_uint(Vs[(wh + mf * 16 + gid + 8) * 20 + kk + tig    ]);
                a[mf][2] = __float_as_uint(Vs[(wh + mf * 16 + gid) * 20     + kk + tig + 4]);
                a[mf][3] = __float_as_uint(Vs[(wh + mf * 16 + gid + 8) * 20 + kk + tig + 4]);
            }
#pragma unroll
            for (int nn = 0; nn < 8; nn++) {
                bb[nn][0] = __float_as_uint(Es[(wn + nn * 8 + gid) * 20 + kk + tig    ]);
                bb[nn][1] = __float_as_uint(Es[(wn + nn * 8 + gid) * 20 + kk + tig + 4]);
            }
#pragma unroll
            for (int mf = 0; mf < 4; mf++)
#pragma unroll
                for (int nn = 0; nn < 8; nn++)
                    mma_tf32(acc[mf][nn], a[mf], bb[nn]);
        }
    };

    const int NC = NDIM / KC;   // 128
    ldg(0);
    sts(0);
    __syncthreads();
#pragma unroll 1
    for (int c = 0; c < NC; c++) {
        if (c + 1 < NC) ldg(c + 1);
        mma_chunk(c & 1);
        if (c + 1 < NC) sts((c + 1) & 1);
        __syncthreads();
    }

    // Epilogue: scale by 1/L[n] and store
    const float* Li = g_L + (size_t)b * NDIM;
#pragma unroll
    for (int nn = 0; nn < 8; nn++) {
        const int col = n0 + wn + nn * 8 + tig * 2;
        const float iv0 = Li[col];
        const float iv1 = Li[col + 1];
#pragma unroll
        for (int mf = 0; mf < 4; mf++) {
            const int row = h0 + wh + mf * 16 + gid;
            *(float2*)(out + (size_t)(b * HDIM + row) * NDIM + col) =
                make_float2(acc[mf][nn][0] * iv0, acc[mf][nn][1] * iv1);
            *(float2*)(out + (size_t)(b * HDIM + row + 8) * NDIM + col) =
                make_float2(acc[mf][nn][2] * iv0, acc[mf][nn][3] * iv1);
        }
    }
}

// ===========================================================================
extern "C" void kernel_launch(void* const* d_in, const int* in_sizes, int n_in,
                              void* d_out, int out_size) {
    const float* q  = (const float*)d_in[0];
    const float* k  = (const float*)d_in[1];
    const float* v  = (const float*)d_in[2];
    const float* pe = (const float*)d_in[3];
    float* out = (float*)d_out;

    cudaFuncSetAttribute(gemm1_k, cudaFuncAttributeMaxDynamicSharedMemorySize, 53248);
    cudaFuncSetAttribute(gemm2_k, cudaFuncAttributeMaxDynamicSharedMemorySize, 61440);

    gemm1_k<<<dim3(8, 16, BATCH), 256, 53248>>>(q, k, pe);
    rowsum_k<<<(BATCH * NDIM) / 256, 256>>>();
    gemm2_k<<<dim3(8, 6, BATCH), 256, 61440>>>(v, out);
}

// round 5
// speedup vs baseline: 1.0035x; 1.0035x over previous
#include <cuda_runtime.h>
#include <math.h>
#include <stdint.h>

#define BATCH 16
#define HDIM  768
#define NDIM  2048
#define KC    16

// Scratch (allocation-free rule: __device__ globals)
__device__ float g_E[(size_t)BATCH * NDIM * NDIM];       // unnormalized exp(logits)
__device__ float g_Lpart[(size_t)BATCH * 8 * NDIM];      // per-mtile partial row sums
__device__ float g_L[(size_t)BATCH * NDIM];              // 1 / rowsum

__device__ __forceinline__ float tf32r(float x) {
    float y;
    asm("cvt.rna.tf32.f32 %0, %1;" : "=f"(y) : "f"(x));
    return y;
}

__device__ __forceinline__ void mma_tf32(float* c, const unsigned* a, const unsigned* b) {
    asm volatile(
        "mma.sync.aligned.m16n8k8.row.col.f32.tf32.tf32.f32 "
        "{%0,%1,%2,%3}, {%4,%5,%6,%7}, {%8,%9}, {%0,%1,%2,%3};\n"
        : "+f"(c[0]), "+f"(c[1]), "+f"(c[2]), "+f"(c[3])
        : "r"(a[0]), "r"(a[1]), "r"(a[2]), "r"(a[3]),
          "r"(b[0]), "r"(b[1]));
}

// ===========================================================================
// GEMM1: S[n][m] = sum_h Q[h][n]*(K[h][m]+PE[h][m]). CTA 128(n) x 256(m).
// 8 warps = 2(n) x 4(m), warp tile 64x64. Double-buffered k-major smem,
// KC=16. Smem (floats): Qs[2][16][136] @0, Ks[2][16][264] @4352, Lred @12800.
// Epilogue: E = exp(S*scale) -> g_E, partial row sums -> g_Lpart.
// ===========================================================================
__global__ __launch_bounds__(256, 1)
void gemm1_k(const float* __restrict__ Q, const float* __restrict__ K,
             const float* __restrict__ PE) {
    extern __shared__ float S[];
    const int b = blockIdx.z, m0 = blockIdx.x * 256, n0 = blockIdx.y * 128;
    const int tid = threadIdx.x, lane = tid & 31, w = tid >> 5;
    const int gid = lane >> 2, tig = lane & 3;
    const int wn = (w & 1) * 64;    // n offset of warp
    const int wm = (w >> 1) * 64;   // m offset of warp

    const float* Qb = Q  + (size_t)b * HDIM * NDIM;
    const float* Kb = K  + (size_t)b * HDIM * NDIM;
    const float* Pb = PE + (size_t)b * HDIM * NDIM;

    float acc[4][8][4];
#pragma unroll
    for (int i = 0; i < 4; i++)
#pragma unroll
        for (int j = 0; j < 8; j++)
#pragma unroll
            for (int r = 0; r < 4; r++) acc[i][j][r] = 0.f;

    float4 qr[2], kr[4];
    const int qrow = tid >> 5, qc = (tid & 31) * 4;   // Q tile: 16 x 128
    const int krow = tid >> 6, kc = (tid & 63) * 4;   // K tile: 16 x 256

    auto ldg = [&](int c) {
        const int h0 = c * KC;
#pragma unroll
        for (int i = 0; i < 2; i++)
            qr[i] = *(const float4*)(Qb + (size_t)(h0 + i * 8 + qrow) * NDIM + n0 + qc);
#pragma unroll
        for (int i = 0; i < 4; i++) {
            const float4 kv = *(const float4*)(Kb + (size_t)(h0 + i * 4 + krow) * NDIM + m0 + kc);
            const float4 pv = *(const float4*)(Pb + (size_t)(h0 + i * 4 + krow) * NDIM + m0 + kc);
            kr[i] = make_float4(kv.x + pv.x, kv.y + pv.y, kv.z + pv.z, kv.w + pv.w);
        }
    };
    auto sts = [&](int s) {
        float* Qs = S + s * 2176;
        float* Ks = S + 4352 + s * 4224;
#pragma unroll
        for (int i = 0; i < 2; i++)
            *(float4*)(Qs + (i * 8 + qrow) * 136 + qc) =
                make_float4(tf32r(qr[i].x), tf32r(qr[i].y), tf32r(qr[i].z), tf32r(qr[i].w));
#pragma unroll
        for (int i = 0; i < 4; i++)
            *(float4*)(Ks + (i * 4 + krow) * 264 + kc) =
                make_float4(tf32r(kr[i].x), tf32r(kr[i].y), tf32r(kr[i].z), tf32r(kr[i].w));
    };
    auto mma_chunk = [&](int s) {
        const float* Qs = S + s * 2176;
        const float* Ks = S + 4352 + s * 4224;
#pragma unroll
        for (int kk = 0; kk < KC; kk += 8) {
            unsigned a[4][4], bb[8][2];
#pragma unroll
            for (int mf = 0; mf < 4; mf++) {
                a[mf][0] = __float_as_uint(Qs[(kk + tig) * 136     + wn + mf * 16 + gid    ]);
                a[mf][1] = __float_as_uint(Qs[(kk + tig) * 136     + wn + mf * 16 + gid + 8]);
                a[mf][2] = __float_as_uint(Qs[(kk + tig + 4) * 136 + wn + mf * 16 + gid    ]);
                a[mf][3] = __float_as_uint(Qs[(kk + tig + 4) * 136 + wn + mf * 16 + gid + 8]);
            }
#pragma unroll
            for (int nn = 0; nn < 8; nn++) {
                bb[nn][0] = __float_as_uint(Ks[(kk + tig) * 264     + wm + nn * 8 + gid]);
                bb[nn][1] = __float_as_uint(Ks[(kk + tig + 4) * 264 + wm + nn * 8 + gid]);
            }
#pragma unroll
            for (int mf = 0; mf < 4; mf++)
#pragma unroll
                for (int nn = 0; nn < 8; nn++)
                    mma_tf32(acc[mf][nn], a[mf], bb[nn]);
        }
    };

    const int NC = HDIM / KC;   // 48
    ldg(0);
    sts(0);
    __syncthreads();
#pragma unroll 1
    for (int c = 0; c < NC; c++) {
        if (c + 1 < NC) ldg(c + 1);
        mma_chunk(c & 1);
        if (c + 1 < NC) sts((c + 1) & 1);
        __syncthreads();
    }

    // Epilogue
    const float scale = 0.03608439182435161f;   // 1/sqrt(768)
    float* Eb = g_E + (size_t)b * NDIM * NDIM;
    float* Lred = S + 12800;
#pragma unroll
    for (int mf = 0; mf < 4; mf++) {
        float rs0 = 0.f, rs1 = 0.f;
#pragma unroll
        for (int nn = 0; nn < 8; nn++) {
            const float e0 = __expf(acc[mf][nn][0] * scale);
            const float e1 = __expf(acc[mf][nn][1] * scale);
            const float e2 = __expf(acc[mf][nn][2] * scale);
            const float e3 = __expf(acc[mf][nn][3] * scale);
            rs0 += e0 + e1;
            rs1 += e2 + e3;
            const int row = n0 + wn + mf * 16 + gid;
            const int col = m0 + wm + nn * 8 + tig * 2;
            *(float2*)(Eb + (size_t)row * NDIM + col)       = make_float2(e0, e1);
            *(float2*)(Eb + (size_t)(row + 8) * NDIM + col) = make_float2(e2, e3);
        }
        rs0 += __shfl_xor_sync(0xffffffffu, rs0, 1);
        rs0 += __shfl_xor_sync(0xffffffffu, rs0, 2);
        rs1 += __shfl_xor_sync(0xffffffffu, rs1, 1);
        rs1 += __shfl_xor_sync(0xffffffffu, rs1, 2);
        if (tig == 0) {
            Lred[(w >> 1) * 128 + wn + mf * 16 + gid]     = rs0;
            Lred[(w >> 1) * 128 + wn + mf * 16 + gid + 8] = rs1;
        }
    }
    __syncthreads();
    if (tid < 128) {
        const float s2 = Lred[tid] + Lred[128 + tid] + Lred[256 + tid] + Lred[384 + tid];
        g_Lpart[((size_t)b * 8 + blockIdx.x) * NDIM + n0 + tid] = s2;
    }
}

// ===========================================================================
// Row-sum reduction -> reciprocal: g_L[b][n] = 1 / sum_j Lpart[b][j][n]
// ===========================================================================
__global__ void rowsum_k() {
    const int t = blockIdx.x * blockDim.x + threadIdx.x;
    const int b = t >> 11, n = t & 2047;
    float s = 0.f;
#pragma unroll
    for (int j = 0; j < 8; j++)
        s += g_Lpart[((size_t)b * 8 + j) * NDIM + n];
    g_L[(size_t)b * NDIM + n] = 1.0f / s;
}

// ===========================================================================
// GEMM2: O[h][n] = (sum_m V[h][m]*E[n][m]) * Linv[n]. CTA 128(h) x 256(n).
// 8 warps = 2(h) x 4(n), warp tile 64x64. Double-buffered [col][k] smem,
// row stride 20 floats (bank-bijective (20*gid+tig) mod 32).
// Smem (floats): Vs[2][128][20] @0, Es[2][256][20] @5120.
// ===========================================================================
__global__ __launch_bounds__(256, 1)
void gemm2_k(const float* __restrict__ V, float* __restrict__ out) {
    extern __shared__ float S[];
    const int b = blockIdx.z, n0 = blockIdx.x * 256, h0 = blockIdx.y * 128;
    const int tid = threadIdx.x, lane = tid & 31, w = tid >> 5;
    const int gid = lane >> 2, tig = lane & 3;
    const int wh = (w & 1) * 64;    // h offset
    const int wn = (w >> 1) * 64;   // n offset

    const float* Vb = V   + (size_t)b * HDIM * NDIM;
    const float* Eb = g_E + (size_t)b * NDIM * NDIM;

    float acc[4][8][4];
#pragma unroll
    for (int i = 0; i < 4; i++)
#pragma unroll
        for (int j = 0; j < 8; j++)
#pragma unroll
            for (int r = 0; r < 4; r++) acc[i][j][r] = 0.f;

    float4 vr[2], er[4];
    const int frow = tid >> 2, fc = (tid & 3) * 4;   // 4 float4 per 16-wide row

    auto ldg = [&](int c) {
        const int mb = c * KC;
#pragma unroll
        for (int i = 0; i < 2; i++)
            vr[i] = *(const float4*)(Vb + (size_t)(h0 + i * 64 + frow) * NDIM + mb + fc);
#pragma unroll
        for (int i = 0; i < 4; i++)
            er[i] = *(const float4*)(Eb + (size_t)(n0 + i * 64 + frow) * NDIM + mb + fc);
    };
    auto sts = [&](int s) {
        float* Vs = S + s * 2560;
        float* Es = S + 5120 + s * 5120;
#pragma unroll
        for (int i = 0; i < 2; i++)
            *(float4*)(Vs + (i * 64 + frow) * 20 + fc) =
                make_float4(tf32r(vr[i].x), tf32r(vr[i].y), tf32r(vr[i].z), tf32r(vr[i].w));
#pragma unroll
        for (int i = 0; i < 4; i++)
            *(float4*)(Es + (i * 64 + frow) * 20 + fc) =
                make_float4(tf32r(er[i].x), tf32r(er[i].y), tf32r(er[i].z), tf32r(er[i].w));
    };
    auto mma_chunk = [&](int s) {
        const float* Vs = S + s * 2560;
        const float* Es = S + 5120 + s * 5120;
#pragma unroll
        for (int kk = 0; kk < KC; kk += 8) {
            unsigned a[4][4], bb[8][2];
#pragma unroll
            for (int mf = 0; mf < 4; mf++) {
                a[mf][0] = __float_as_uint(Vs[(wh + mf * 16 + gid) * 20     + kk + tig    ]);
                a[mf][1] = __float_as_uint(Vs[(wh + mf * 16 + gid + 8) * 20 + kk + tig    ]);
                a[mf][2] = __float_as_uint(Vs[(wh + mf * 16 + gid) * 20     + kk + tig + 4]);
                a[mf][3] = __float_as_uint(Vs[(wh + mf * 16 + gid + 8) * 20 + kk + tig + 4]);
            }
#pragma unroll
            for (int nn = 0; nn < 8; nn++) {
                bb[nn][0] = __float_as_uint(Es[(wn + nn * 8 + gid) * 20 + kk + tig    ]);
                bb[nn][1] = __float_as_uint(Es[(wn + nn * 8 + gid) * 20 + kk + tig + 4]);
            }
#pragma unroll
            for (int mf = 0; mf < 4; mf++)
#pragma unroll
                for (int nn = 0; nn < 8; nn++)
                    mma_tf32(acc[mf][nn], a[mf], bb[nn]);
        }
    };

    const int NC = NDIM / KC;   // 128
    ldg(0);
    sts(0);
    __syncthreads();
#pragma unroll 1
    for (int c = 0; c < NC; c++) {
        if (c + 1 < NC) ldg(c + 1);
        mma_chunk(c & 1);
        if (c + 1 < NC) sts((c + 1) & 1);
        __syncthreads();
    }

    // Epilogue: scale by 1/L[n] and store
    const float* Li = g_L + (size_t)b * NDIM;
#pragma unroll
    for (int nn = 0; nn < 8; nn++) {
        const int col = n0 + wn + nn * 8 + tig * 2;
        const float iv0 = Li[col];
        const float iv1 = Li[col + 1];
#pragma unroll
        for (int mf = 0; mf < 4; mf++) {
            const int row = h0 + wh + mf * 16 + gid;
            *(float2*)(out + (size_t)(b * HDIM + row) * NDIM + col) =
                make_float2(acc[mf][nn][0] * iv0, acc[mf][nn][1] * iv1);
            *(float2*)(out + (size_t)(b * HDIM + row + 8) * NDIM + col) =
                make_float2(acc[mf][nn][2] * iv0, acc[mf][nn][3] * iv1);
        }
    }
}

// ===========================================================================
extern "C" void kernel_launch(void* const* d_in, const int* in_sizes, int n_in,
                              void* d_out, int out_size) {
    const float* q  = (const float*)d_in[0];
    const float* k  = (const float*)d_in[1];
    const float* v  = (const float*)d_in[2];
    const float* pe = (const float*)d_in[3];
    float* out = (float*)d_out;

    cudaFuncSetAttribute(gemm1_k, cudaFuncAttributeMaxDynamicSharedMemorySize, 53248);
    cudaFuncSetAttribute(gemm2_k, cudaFuncAttributeMaxDynamicSharedMemorySize, 61440);

    gemm1_k<<<dim3(8, 16, BATCH), 256, 53248>>>(q, k, pe);
    rowsum_k<<<(BATCH * NDIM) / 256, 256>>>();
    gemm2_k<<<dim3(8, 6, BATCH), 256, 61440>>>(v, out);
}

// round 6
// speedup vs baseline: 1.9946x; 1.9875x over previous
#include <cuda_runtime.h>
#include <cuda_fp16.h>
#include <math.h>
#include <stdint.h>

#define BATCH 16
#define HDIM  768
#define NDIM  2048
#define KC    32            // k elements per chunk (fp16)
#define PITCH 40            // smem row pitch in halfs (80B, bank-bijective)
#define STAGE_A (128 * PITCH)
#define STAGE_B (256 * PITCH)
#define STAGE   (STAGE_A + STAGE_B)          // halfs per stage (15360 = 30720B)
#define SMEM_BYTES (4 * STAGE * 2 + 2048)    // 4 stages + Lred

// Scratch (allocation-free rule: __device__ globals)
__device__ __half g_Qt[(size_t)BATCH * NDIM * HDIM];  // [b][n][h]
__device__ __half g_Kt[(size_t)BATCH * NDIM * HDIM];  // [b][m][h] = fp16(K+PE)
__device__ __half g_Vh[(size_t)BATCH * HDIM * NDIM];  // [b][h][m]
__device__ __half g_Eh[(size_t)BATCH * NDIM * NDIM];  // [b][n][m] exp(logits)
__device__ float  g_Lpart[(size_t)BATCH * 8 * NDIM];
__device__ float  g_L[(size_t)BATCH * NDIM];          // 1 / rowsum

__device__ __forceinline__ uint32_t smem_u32(const void* p) {
    uint32_t a;
    asm("{ .reg .u64 t; cvta.to.shared.u64 t, %1; cvt.u32.u64 %0, t; }" : "=r"(a) : "l"(p));
    return a;
}
__device__ __forceinline__ void cpa16(uint32_t dst, const void* src) {
    asm volatile("cp.async.cg.shared.global [%0], [%1], 16;" :: "r"(dst), "l"(src));
}
#define CP_COMMIT() asm volatile("cp.async.commit_group;" ::: "memory")
#define CP_WAIT2()  asm volatile("cp.async.wait_group 2;" ::: "memory")

__device__ __forceinline__ void mma_f16(float* c, const uint32_t* a, const uint32_t* b) {
    asm volatile(
        "mma.sync.aligned.m16n8k16.row.col.f32.f16.f16.f32 "
        "{%0,%1,%2,%3}, {%4,%5,%6,%7}, {%8,%9}, {%0,%1,%2,%3};\n"
        : "+f"(c[0]), "+f"(c[1]), "+f"(c[2]), "+f"(c[3])
        : "r"(a[0]), "r"(a[1]), "r"(a[2]), "r"(a[3]), "r"(b[0]), "r"(b[1]));
}

// ===========================================================================
// Pre-pass 1: transpose+convert.  Qt[b][n][h]=h(Q[b][h][n]); Kt[b][m][h]=h(K+PE)
// ===========================================================================
__global__ __launch_bounds__(256)
void prep_qk(const float* __restrict__ Q, const float* __restrict__ K,
             const float* __restrict__ PE) {
    __shared__ float t[32][33];
    const int b = blockIdx.z, h0 = blockIdx.y * 32, n0 = blockIdx.x * 32;
    const int tx = threadIdx.x & 31, ty = threadIdx.x >> 5;
    const size_t ibase = (size_t)b * HDIM * NDIM;
    const size_t obase = (size_t)b * NDIM * HDIM;

#pragma unroll
    for (int j = 0; j < 4; j++)
        t[ty + j * 8][tx] = Q[ibase + (size_t)(h0 + ty + j * 8) * NDIM + n0 + tx];
    __syncthreads();
#pragma unroll
    for (int j = 0; j < 4; j++)
        g_Qt[obase + (size_t)(n0 + ty + j * 8) * HDIM + h0 + tx] =
            __float2half_rn(t[tx][ty + j * 8]);
    __syncthreads();
#pragma unroll
    for (int j = 0; j < 4; j++) {
        const size_t idx = ibase + (size_t)(h0 + ty + j * 8) * NDIM + n0 + tx;
        t[ty + j * 8][tx] = K[idx] + PE[idx];
    }
    __syncthreads();
#pragma unroll
    for (int j = 0; j < 4; j++)
        g_Kt[obase + (size_t)(n0 + ty + j * 8) * HDIM + h0 + tx] =
            __float2half_rn(t[tx][ty + j * 8]);
}

// Pre-pass 2: V -> fp16 elementwise
__global__ __launch_bounds__(256)
void conv_v(const float* __restrict__ V) {
    const size_t i = ((size_t)blockIdx.x * 256 + threadIdx.x) * 4;
    float4 v = *(const float4*)(V + i);
    __half2 a = __floats2half2_rn(v.x, v.y);
    __half2 b = __floats2half2_rn(v.z, v.w);
    *(uint2*)(g_Vh + i) = make_uint2(*(uint32_t*)&a, *(uint32_t*)&b);
}

// ===========================================================================
// GEMM1: S[n][m] = sum_h Qt[n][h]*Kt[m][h]. CTA 128(n) x 256(m), 8 warps as
// 2(n) x 4(m), warp tile 64x64. 4-stage cp.async pipeline, KC=32.
// Epilogue: Eh = fp16(exp(S*scale)); partial rowsums of rounded values.
// ===========================================================================
__global__ __launch_bounds__(256)
void gemm1_k() {
    extern __shared__ __half S[];
    const int b = blockIdx.z, m0 = blockIdx.x * 256, n0 = blockIdx.y * 128;
    const int tid = threadIdx.x, lane = tid & 31, w = tid >> 5;
    const int gid = lane >> 2, tig = lane & 3;
    const int wn = (w & 1) * 64;    // n offset (A rows)
    const int wm = (w >> 1) * 64;   // m offset (B rows)

    const __half* Qb = g_Qt + (size_t)b * NDIM * HDIM + (size_t)n0 * HDIM;
    const __half* Kb = g_Kt + (size_t)b * NDIM * HDIM + (size_t)m0 * HDIM;
    const uint32_t sbase = smem_u32(S);

    float acc[4][8][4];
#pragma unroll
    for (int i = 0; i < 4; i++)
#pragma unroll
        for (int j = 0; j < 8; j++)
#pragma unroll
            for (int r = 0; r < 4; r++) acc[i][j][r] = 0.f;

    auto fill = [&](int c, int stg) {
        const int hc = c * KC;
        const uint32_t dA = sbase + stg * STAGE * 2;
        const uint32_t dB = dA + STAGE_A * 2;
#pragma unroll
        for (int i = 0; i < 2; i++) {           // A: 128 rows x 4 units
            const int idx = i * 256 + tid, row = idx >> 2, u = idx & 3;
            cpa16(dA + (row * PITCH + u * 8) * 2, Qb + (size_t)row * HDIM + hc + u * 8);
        }
#pragma unroll
        for (int i = 0; i < 4; i++) {           // B: 256 rows x 4 units
            const int idx = i * 256 + tid, row = idx >> 2, u = idx & 3;
            cpa16(dB + (row * PITCH + u * 8) * 2, Kb + (size_t)row * HDIM + hc + u * 8);
        }
        CP_COMMIT();
    };

    const int NC = HDIM / KC;   // 24
    fill(0, 0); fill(1, 1); fill(2, 2);
#pragma unroll 1
    for (int c = 0; c < NC; c++) {
        CP_WAIT2();
        __syncthreads();
        if (c + 3 < NC) fill(c + 3, (c + 3) & 3); else CP_COMMIT();
        const __half* As = S + (c & 3) * STAGE;
        const __half* Bs = As + STAGE_A;
#pragma unroll
        for (int ks = 0; ks < 2; ks++) {
            const int kh = ks * 16 + tig * 2;
            uint32_t a[4][4], bb[8][2];
#pragma unroll
            for (int mf = 0; mf < 4; mf++) {
                const __half* p = As + (wn + mf * 16 + gid) * PITCH + kh;
                a[mf][0] = *(const uint32_t*)p;
                a[mf][1] = *(const uint32_t*)(p + 8 * PITCH);
                a[mf][2] = *(const uint32_t*)(p + 8);
                a[mf][3] = *(const uint32_t*)(p + 8 * PITCH + 8);
            }
#pragma unroll
            for (int nf = 0; nf < 8; nf++) {
                const __half* p = Bs + (wm + nf * 8 + gid) * PITCH + kh;
                bb[nf][0] = *(const uint32_t*)p;
                bb[nf][1] = *(const uint32_t*)(p + 8);
            }
#pragma unroll
            for (int mf = 0; mf < 4; mf++)
#pragma unroll
                for (int nf = 0; nf < 8; nf++)
                    mma_f16(acc[mf][nf], a[mf], bb[nf]);
        }
    }
    __syncthreads();

    // Epilogue: round to fp16, store E, rowsum of rounded values.
    const float scale = 0.03608439182435161f;   // 1/sqrt(768)
    __half* Eb = g_Eh + (size_t)b * NDIM * NDIM;
    float* Lred = (float*)(S + 4 * STAGE);
#pragma unroll
    for (int mf = 0; mf < 4; mf++) {
        float rs0 = 0.f, rs1 = 0.f;
#pragma unroll
        for (int nf = 0; nf < 8; nf++) {
            __half2 h01 = __floats2half2_rn(__expf(acc[mf][nf][0] * scale),
                                            __expf(acc[mf][nf][1] * scale));
            __half2 h23 = __floats2half2_rn(__expf(acc[mf][nf][2] * scale),
                                            __expf(acc[mf][nf][3] * scale));
            float2 f01 = __half22float2(h01);
            float2 f23 = __half22float2(h23);
            rs0 += f01.x + f01.y;
            rs1 += f23.x + f23.y;
            const int row = n0 + wn + mf * 16 + gid;
            const int col = m0 + wm + nf * 8 + tig * 2;
            *(__half2*)(Eb + (size_t)row * NDIM + col)       = h01;
            *(__half2*)(Eb + (size_t)(row + 8) * NDIM + col) = h23;
        }
        rs0 += __shfl_xor_sync(0xffffffffu, rs0, 1);
        rs0 += __shfl_xor_sync(0xffffffffu, rs0, 2);
        rs1 += __shfl_xor_sync(0xffffffffu, rs1, 1);
        rs1 += __shfl_xor_sync(0xffffffffu, rs1, 2);
        if (tig == 0) {
            Lred[(w >> 1) * 128 + wn + mf * 16 + gid]     = rs0;
            Lred[(w >> 1) * 128 + wn + mf * 16 + gid + 8] = rs1;
        }
    }
    __syncthreads();
    if (tid < 128) {
        const float s = Lred[tid] + Lred[128 + tid] + Lred[256 + tid] + Lred[384 + tid];
        g_Lpart[((size_t)b * 8 + blockIdx.x) * NDIM + n0 + tid] = s;
    }
}

// ===========================================================================
__global__ void rowsum_k() {
    const int t = blockIdx.x * blockDim.x + threadIdx.x;
    const int b = t >> 11, n = t & 2047;
    float s = 0.f;
#pragma unroll
    for (int j = 0; j < 8; j++)
        s += g_Lpart[((size_t)b * 8 + j) * NDIM + n];
    g_L[(size_t)b * NDIM + n] = 1.0f / s;
}

// ===========================================================================
// GEMM2: O[h][n] = (sum_m Vh[h][m]*Eh[n][m]) * Linv[n]. CTA 128(h) x 256(n),
// warp tile 64x64, same 4-stage pipeline, KC=32 over m.
// ===========================================================================
__global__ __launch_bounds__(256)
void gemm2_k(float* __restrict__ out) {
    extern __shared__ __half S[];
    const int b = blockIdx.z, n0 = blockIdx.x * 256, h0 = blockIdx.y * 128;
    const int tid = threadIdx.x, lane = tid & 31, w = tid >> 5;
    const int gid = lane >> 2, tig = lane & 3;
    const int wh = (w & 1) * 64;    // h offset (A rows)
    const int wn = (w >> 1) * 64;   // n offset (B rows)

    const __half* Vb = g_Vh + (size_t)b * HDIM * NDIM + (size_t)h0 * NDIM;
    const __half* Eb = g_Eh + (size_t)b * NDIM * NDIM + (size_t)n0 * NDIM;
    const uint32_t sbase = smem_u32(S);

    float acc[4][8][4];
#pragma unroll
    for (int i = 0; i < 4; i++)
#pragma unroll
        for (int j = 0; j < 8; j++)
#pragma unroll
            for (int r = 0; r < 4; r++) acc[i][j][r] = 0.f;

    auto fill = [&](int c, int stg) {
        const int mc = c * KC;
        const uint32_t dA = sbase + stg * STAGE * 2;
        const uint32_t dB = dA + STAGE_A * 2;
#pragma unroll
        for (int i = 0; i < 2; i++) {
            const int idx = i * 256 + tid, row = idx >> 2, u = idx & 3;
            cpa16(dA + (row * PITCH + u * 8) * 2, Vb + (size_t)row * NDIM + mc + u * 8);
        }
#pragma unroll
        for (int i = 0; i < 4; i++) {
            const int idx = i * 256 + tid, row = idx >> 2, u = idx & 3;
            cpa16(dB + (row * PITCH + u * 8) * 2, Eb + (size_t)row * NDIM + mc + u * 8);
        }
        CP_COMMIT();
    };

    const int NC = NDIM / KC;   // 64
    fill(0, 0); fill(1, 1); fill(2, 2);
#pragma unroll 1
    for (int c = 0; c < NC; c++) {
        CP_WAIT2();
        __syncthreads();
        if (c + 3 < NC) fill(c + 3, (c + 3) & 3); else CP_COMMIT();
        const __half* As = S + (c & 3) * STAGE;
        const __half* Bs = As + STAGE_A;
#pragma unroll
        for (int ks = 0; ks < 2; ks++) {
            const int kh = ks * 16 + tig * 2;
            uint32_t a[4][4], bb[8][2];
#pragma unroll
            for (int mf = 0; mf < 4; mf++) {
                const __half* p = As + (wh + mf * 16 + gid) * PITCH + kh;
                a[mf][0] = *(const uint32_t*)p;
                a[mf][1] = *(const uint32_t*)(p + 8 * PITCH);
                a[mf][2] = *(const uint32_t*)(p + 8);
                a[mf][3] = *(const uint32_t*)(p + 8 * PITCH + 8);
            }
#pragma unroll
            for (int nf = 0; nf < 8; nf++) {
                const __half* p = Bs + (wn + nf * 8 + gid) * PITCH + kh;
                bb[nf][0] = *(const uint32_t*)p;
                bb[nf][1] = *(const uint32_t*)(p + 8);
            }
#pragma unroll
            for (int mf = 0; mf < 4; mf++)
#pragma unroll
                for (int nf = 0; nf < 8; nf++)
                    mma_f16(acc[mf][nf], a[mf], bb[nf]);
        }
    }

    // Epilogue: multiply by 1/L[n], store fp32
    const float* Li = g_L + (size_t)b * NDIM;
#pragma unroll
    for (int nf = 0; nf < 8; nf++) {
        const int col = n0 + wn + nf * 8 + tig * 2;
        const float iv0 = Li[col], iv1 = Li[col + 1];
#pragma unroll
        for (int mf = 0; mf < 4; mf++) {
            const int row = h0 + wh + mf * 16 + gid;
            *(float2*)(out + (size_t)(b * HDIM + row) * NDIM + col) =
                make_float2(acc[mf][nf][0] * iv0, acc[mf][nf][1] * iv1);
            *(float2*)(out + (size_t)(b * HDIM + row + 8) * NDIM + col) =
                make_float2(acc[mf][nf][2] * iv0, acc[mf][nf][3] * iv1);
        }
    }
}

// ===========================================================================
extern "C" void kernel_launch(void* const* d_in, const int* in_sizes, int n_in,
                              void* d_out, int out_size) {
    const float* q  = (const float*)d_in[0];
    const float* k  = (const float*)d_in[1];
    const float* v  = (const float*)d_in[2];
    const float* pe = (const float*)d_in[3];
    float* out = (float*)d_out;

    cudaFuncSetAttribute(gemm1_k, cudaFuncAttributeMaxDynamicSharedMemorySize, SMEM_BYTES);
    cudaFuncSetAttribute(gemm2_k, cudaFuncAttributeMaxDynamicSharedMemorySize, SMEM_BYTES);

    prep_qk<<<dim3(NDIM / 32, HDIM / 32, BATCH), 256>>>(q, k, pe);
    conv_v<<<(BATCH * HDIM * NDIM) / 1024, 256>>>(v);
    gemm1_k<<<dim3(8, 16, BATCH), 256, SMEM_BYTES>>>();
    rowsum_k<<<(BATCH * NDIM) / 256, 256>>>();
    gemm2_k<<<dim3(8, 6, BATCH), 256, SMEM_BYTES>>>(out);
}

// round 7
// speedup vs baseline: 2.0159x; 1.0107x over previous
#include <cuda_runtime.h>
#include <cuda_fp16.h>
#include <math.h>
#include <stdint.h>

#define BATCH 16
#define HDIM  768
#define NDIM  2048
#define KC    32            // k elements per chunk (fp16)
#define PITCH 40            // smem row pitch in halfs (80B, bank-bijective + LDSM-clean)
#define STAGE_A (128 * PITCH)
#define STAGE_B (256 * PITCH)
#define STAGE   (STAGE_A + STAGE_B)          // halfs per stage (15360 = 30720B)
#define SMEM_BYTES (4 * STAGE * 2 + 2048)    // 4 stages + Lred

// Scratch (allocation-free rule: __device__ globals)
__device__ __half g_Qt[(size_t)BATCH * NDIM * HDIM];  // [b][n][h]
__device__ __half g_Kt[(size_t)BATCH * NDIM * HDIM];  // [b][m][h] = fp16(K+PE)
__device__ __half g_Vh[(size_t)BATCH * HDIM * NDIM];  // [b][h][m]
__device__ __half g_Eh[(size_t)BATCH * NDIM * NDIM];  // [b][n][m] exp(logits)
__device__ float  g_Lpart[(size_t)BATCH * 8 * NDIM];
__device__ float  g_L[(size_t)BATCH * NDIM];          // 1 / rowsum

__device__ __forceinline__ uint32_t smem_u32(const void* p) {
    uint32_t a;
    asm("{ .reg .u64 t; cvta.to.shared.u64 t, %1; cvt.u32.u64 %0, t; }" : "=r"(a) : "l"(p));
    return a;
}
__device__ __forceinline__ void cpa16(uint32_t dst, const void* src) {
    asm volatile("cp.async.cg.shared.global [%0], [%1], 16;" :: "r"(dst), "l"(src));
}
#define CP_COMMIT() asm volatile("cp.async.commit_group;" ::: "memory")
#define CP_WAIT2()  asm volatile("cp.async.wait_group 2;" ::: "memory")

#define LDSM_X4(r0, r1, r2, r3, addr) \
    asm volatile("ldmatrix.sync.aligned.m8n8.x4.shared.b16 {%0,%1,%2,%3}, [%4];" \
                 : "=r"(r0), "=r"(r1), "=r"(r2), "=r"(r3) : "r"(addr))

__device__ __forceinline__ void mma_f16(float* c, const uint32_t* a, const uint32_t* b) {
    asm volatile(
        "mma.sync.aligned.m16n8k16.row.col.f32.f16.f16.f32 "
        "{%0,%1,%2,%3}, {%4,%5,%6,%7}, {%8,%9}, {%0,%1,%2,%3};\n"
        : "+f"(c[0]), "+f"(c[1]), "+f"(c[2]), "+f"(c[3])
        : "r"(a[0]), "r"(a[1]), "r"(a[2]), "r"(a[3]), "r"(b[0]), "r"(b[1]));
}

// ===========================================================================
// Pre-pass 1: transpose+convert.  Qt[b][n][h]=h(Q[b][h][n]); Kt[b][m][h]=h(K+PE)
// ===========================================================================
__global__ __launch_bounds__(256)
void prep_qk(const float* __restrict__ Q, const float* __restrict__ K,
             const float* __restrict__ PE) {
    __shared__ float t[32][33];
    const int b = blockIdx.z, h0 = blockIdx.y * 32, n0 = blockIdx.x * 32;
    const int tx = threadIdx.x & 31, ty = threadIdx.x >> 5;
    const size_t ibase = (size_t)b * HDIM * NDIM;
    const size_t obase = (size_t)b * NDIM * HDIM;

#pragma unroll
    for (int j = 0; j < 4; j++)
        t[ty + j * 8][tx] = Q[ibase + (size_t)(h0 + ty + j * 8) * NDIM + n0 + tx];
    __syncthreads();
#pragma unroll
    for (int j = 0; j < 4; j++)
        g_Qt[obase + (size_t)(n0 + ty + j * 8) * HDIM + h0 + tx] =
            __float2half_rn(t[tx][ty + j * 8]);
    __syncthreads();
#pragma unroll
    for (int j = 0; j < 4; j++) {
        const size_t idx = ibase + (size_t)(h0 + ty + j * 8) * NDIM + n0 + tx;
        t[ty + j * 8][tx] = K[idx] + PE[idx];
    }
    __syncthreads();
#pragma unroll
    for (int j = 0; j < 4; j++)
        g_Kt[obase + (size_t)(n0 + ty + j * 8) * HDIM + h0 + tx] =
            __float2half_rn(t[tx][ty + j * 8]);
}

// Pre-pass 2: V -> fp16 elementwise
__global__ __launch_bounds__(256)
void conv_v(const float* __restrict__ V) {
    const size_t i = ((size_t)blockIdx.x * 256 + threadIdx.x) * 4;
    float4 v = *(const float4*)(V + i);
    __half2 a = __floats2half2_rn(v.x, v.y);
    __half2 b = __floats2half2_rn(v.z, v.w);
    *(uint2*)(g_Vh + i) = make_uint2(*(uint32_t*)&a, *(uint32_t*)&b);
}

// ===========================================================================
// Shared mainloop fragment math (A rows = warp_m base wa, B rows = warp_n wb).
// Per ks (16 k): 4 LDSM.x4 (A) + 4 LDSM.x4 (B) + 32 HMMA.
// ===========================================================================
struct Frag { uint32_t a[4][4], b[8][2]; };

__device__ __forceinline__ void mma_chunk(float acc[4][8][4], uint32_t stA, uint32_t stB,
                                          int wa, int wb, int lane) {
    // lane-invariant offsets
    const uint32_t aoff = stA + ((uint32_t)(wa + (lane & 15)) * PITCH + ((lane >> 4) * 8)) * 2;
    const uint32_t boff = stB + ((uint32_t)(wb + ((lane & 7) | ((lane & 16) >> 1))) * PITCH
                                 + (((lane >> 3) & 1) * 8)) * 2;
#pragma unroll
    for (int ks = 0; ks < 2; ks++) {
        Frag f;
        const uint32_t kb = ks * 32;   // 16 halfs = 32 bytes
#pragma unroll
        for (int mf = 0; mf < 4; mf++)
            LDSM_X4(f.a[mf][0], f.a[mf][1], f.a[mf][2], f.a[mf][3],
                    aoff + kb + mf * (16 * PITCH * 2));
#pragma unroll
        for (int n2 = 0; n2 < 4; n2++)
            LDSM_X4(f.b[2 * n2][0], f.b[2 * n2][1], f.b[2 * n2 + 1][0], f.b[2 * n2 + 1][1],
                    boff + kb + n2 * (16 * PITCH * 2));
#pragma unroll
        for (int mf = 0; mf < 4; mf++)
#pragma unroll
            for (int nf = 0; nf < 8; nf++)
                mma_f16(acc[mf][nf], f.a[mf], f.b[nf]);
    }
}

// ===========================================================================
// GEMM1: S[n][m] = sum_h Qt[n][h]*Kt[m][h]. CTA 128(n) x 256(m), 8 warps as
// 2(n) x 4(m), warp tile 64x64. 4-stage cp.async pipeline, KC=32.
// ===========================================================================
__global__ __launch_bounds__(256)
void gemm1_k() {
    extern __shared__ __half S[];
    const int b = blockIdx.z, m0 = blockIdx.x * 256, n0 = blockIdx.y * 128;
    const int tid = threadIdx.x, lane = tid & 31, w = tid >> 5;
    const int gid = lane >> 2, tig = lane & 3;
    const int wn = (w & 1) * 64;    // n offset (A rows)
    const int wm = (w >> 1) * 64;   // m offset (B rows)

    const __half* Qb = g_Qt + (size_t)b * NDIM * HDIM + (size_t)n0 * HDIM;
    const __half* Kb = g_Kt + (size_t)b * NDIM * HDIM + (size_t)m0 * HDIM;
    const uint32_t sbase = smem_u32(S);

    float acc[4][8][4];
#pragma unroll
    for (int i = 0; i < 4; i++)
#pragma unroll
        for (int j = 0; j < 8; j++)
#pragma unroll
            for (int r = 0; r < 4; r++) acc[i][j][r] = 0.f;

    auto fill = [&](int c, int stg) {
        const int hc = c * KC;
        const uint32_t dA = sbase + stg * STAGE * 2;
        const uint32_t dB = dA + STAGE_A * 2;
#pragma unroll
        for (int i = 0; i < 2; i++) {
            const int idx = i * 256 + tid, row = idx >> 2, u = idx & 3;
            cpa16(dA + (row * PITCH + u * 8) * 2, Qb + (size_t)row * HDIM + hc + u * 8);
        }
#pragma unroll
        for (int i = 0; i < 4; i++) {
            const int idx = i * 256 + tid, row = idx >> 2, u = idx & 3;
            cpa16(dB + (row * PITCH + u * 8) * 2, Kb + (size_t)row * HDIM + hc + u * 8);
        }
        CP_COMMIT();
    };

    const int NC = HDIM / KC;   // 24
    fill(0, 0); fill(1, 1); fill(2, 2);
#pragma unroll 1
    for (int c = 0; c < NC; c++) {
        CP_WAIT2();
        __syncthreads();
        if (c + 3 < NC) fill(c + 3, (c + 3) & 3); else CP_COMMIT();
        const uint32_t stA = sbase + (c & 3) * STAGE * 2;
        mma_chunk(acc, stA, stA + STAGE_A * 2, wn, wm, lane);
    }
    __syncthreads();

    // Epilogue: round to fp16, store E, rowsum of rounded values.
    const float scale = 0.03608439182435161f;   // 1/sqrt(768)
    __half* Eb = g_Eh + (size_t)b * NDIM * NDIM;
    float* Lred = (float*)(S + 4 * STAGE);
#pragma unroll
    for (int mf = 0; mf < 4; mf++) {
        float rs0 = 0.f, rs1 = 0.f;
#pragma unroll
        for (int nf = 0; nf < 8; nf++) {
            __half2 h01 = __floats2half2_rn(__expf(acc[mf][nf][0] * scale),
                                            __expf(acc[mf][nf][1] * scale));
            __half2 h23 = __floats2half2_rn(__expf(acc[mf][nf][2] * scale),
                                            __expf(acc[mf][nf][3] * scale));
            float2 f01 = __half22float2(h01);
            float2 f23 = __half22float2(h23);
            rs0 += f01.x + f01.y;
            rs1 += f23.x + f23.y;
            const int row = n0 + wn + mf * 16 + gid;
            const int col = m0 + wm + nf * 8 + tig * 2;
            *(__half2*)(Eb + (size_t)row * NDIM + col)       = h01;
            *(__half2*)(Eb + (size_t)(row + 8) * NDIM + col) = h23;
        }
        rs0 += __shfl_xor_sync(0xffffffffu, rs0, 1);
        rs0 += __shfl_xor_sync(0xffffffffu, rs0, 2);
        rs1 += __shfl_xor_sync(0xffffffffu, rs1, 1);
        rs1 += __shfl_xor_sync(0xffffffffu, rs1, 2);
        if (tig == 0) {
            Lred[(w >> 1) * 128 + wn + mf * 16 + gid]     = rs0;
            Lred[(w >> 1) * 128 + wn + mf * 16 + gid + 8] = rs1;
        }
    }
    __syncthreads();
    if (tid < 128) {
        const float s = Lred[tid] + Lred[128 + tid] + Lred[256 + tid] + Lred[384 + tid];
        g_Lpart[((size_t)b * 8 + blockIdx.x) * NDIM + n0 + tid] = s;
    }
}

// ===========================================================================
__global__ void rowsum_k() {
    const int t = blockIdx.x * blockDim.x + threadIdx.x;
    const int b = t >> 11, n = t & 2047;
    float s = 0.f;
#pragma unroll
    for (int j = 0; j < 8; j++)
        s += g_Lpart[((size_t)b * 8 + j) * NDIM + n];
    g_L[(size_t)b * NDIM + n] = 1.0f / s;
}

// ===========================================================================
// GEMM2: O[h][n] = (sum_m Vh[h][m]*Eh[n][m]) * Linv[n]. CTA 128(h) x 256(n).
// ===========================================================================
__global__ __launch_bounds__(256)
void gemm2_k(float* __restrict__ out) {
    extern __shared__ __half S[];
    const int b = blockIdx.z, n0 = blockIdx.x * 256, h0 = blockIdx.y * 128;
    const int tid = threadIdx.x, lane = tid & 31, w = tid >> 5;
    const int gid = lane >> 2, tig = lane & 3;
    const int wh = (w & 1) * 64;    // h offset (A rows)
    const int wn = (w >> 1) * 64;   // n offset (B rows)

    const __half* Vb = g_Vh + (size_t)b * HDIM * NDIM + (size_t)h0 * NDIM;
    const __half* Eb = g_Eh + (size_t)b * NDIM * NDIM + (size_t)n0 * NDIM;
    const uint32_t sbase = smem_u32(S);

    float acc[4][8][4];
#pragma unroll
    for (int i = 0; i < 4; i++)
#pragma unroll
        for (int j = 0; j < 8; j++)
#pragma unroll
            for (int r = 0; r < 4; r++) acc[i][j][r] = 0.f;

    auto fill = [&](int c, int stg) {
        const int mc = c * KC;
        const uint32_t dA = sbase + stg * STAGE * 2;
        const uint32_t dB = dA + STAGE_A * 2;
#pragma unroll
        for (int i = 0; i < 2; i++) {
            const int idx = i * 256 + tid, row = idx >> 2, u = idx & 3;
            cpa16(dA + (row * PITCH + u * 8) * 2, Vb + (size_t)row * NDIM + mc + u * 8);
        }
#pragma unroll
        for (int i = 0; i < 4; i++) {
            const int idx = i * 256 + tid, row = idx >> 2, u = idx & 3;
            cpa16(dB + (row * PITCH + u * 8) * 2, Eb + (size_t)row * NDIM + mc + u * 8);
        }
        CP_COMMIT();
    };

    const int NC = NDIM / KC;   // 64
    fill(0, 0); fill(1, 1); fill(2, 2);
#pragma unroll 1
    for (int c = 0; c < NC; c++) {
        CP_WAIT2();
        __syncthreads();
        if (c + 3 < NC) fill(c + 3, (c + 3) & 3); else CP_COMMIT();
        const uint32_t stA = sbase + (c & 3) * STAGE * 2;
        mma_chunk(acc, stA, stA + STAGE_A * 2, wh, wn, lane);
    }

    // Epilogue: multiply by 1/L[n], store fp32
    const float* Li = g_L + (size_t)b * NDIM;
#pragma unroll
    for (int nf = 0; nf < 8; nf++) {
        const int col = n0 + wn + nf * 8 + tig * 2;
        const float iv0 = Li[col], iv1 = Li[col + 1];
#pragma unroll
        for (int mf = 0; mf < 4; mf++) {
            const int row = h0 + wh + mf * 16 + gid;
            *(float2*)(out + (size_t)(b * HDIM + row) * NDIM + col) =
                make_float2(acc[mf][nf][0] * iv0, acc[mf][nf][1] * iv1);
            *(float2*)(out + (size_t)(b * HDIM + row + 8) * NDIM + col) =
                make_float2(acc[mf][nf][2] * iv0, acc[mf][nf][3] * iv1);
        }
    }
}

// ===========================================================================
extern "C" void kernel_launch(void* const* d_in, const int* in_sizes, int n_in,
                              void* d_out, int out_size) {
    const float* q  = (const float*)d_in[0];
    const float* k  = (const float*)d_in[1];
    const float* v  = (const float*)d_in[2];
    const float* pe = (const float*)d_in[3];
    float* out = (float*)d_out;

    cudaFuncSetAttribute(gemm1_k, cudaFuncAttributeMaxDynamicSharedMemorySize, SMEM_BYTES);
    cudaFuncSetAttribute(gemm2_k, cudaFuncAttributeMaxDynamicSharedMemorySize, SMEM_BYTES);

    prep_qk<<<dim3(NDIM / 32, HDIM / 32, BATCH), 256>>>(q, k, pe);
    conv_v<<<(BATCH * HDIM * NDIM) / 1024, 256>>>(v);
    gemm1_k<<<dim3(8, 16, BATCH), 256, SMEM_BYTES>>>();
    rowsum_k<<<(BATCH * NDIM) / 256, 256>>>();
    gemm2_k<<<dim3(8, 6, BATCH), 256, SMEM_BYTES>>>(out);
}

// round 8
// speedup vs baseline: 2.0545x; 1.0191x over previous
#include <cuda_runtime.h>
#include <cuda_fp16.h>
#include <math.h>
#include <stdint.h>

#define BATCH 16
#define HDIM  768
#define NDIM  2048
#define KC    32            // k elements per chunk (fp16)
#define PITCH 40            // smem row pitch in halfs (80B, bank-bijective + LDSM-clean)
#define STAGE_A (128 * PITCH)
#define STAGE_B (256 * PITCH)
#define STAGE   (STAGE_A + STAGE_B)          // halfs per stage (15360 = 30720B)
#define NTHREADS 512
#define SMEM_BYTES (4 * STAGE * 2 + 4096)    // 4 stages + Lred (8*128 floats)

// Scratch (allocation-free rule: __device__ globals)
__device__ __half g_Qt[(size_t)BATCH * NDIM * HDIM];  // [b][n][h]
__device__ __half g_Kt[(size_t)BATCH * NDIM * HDIM];  // [b][m][h] = fp16(K+PE)
__device__ __half g_Vh[(size_t)BATCH * HDIM * NDIM];  // [b][h][m]
__device__ __half g_Eh[(size_t)BATCH * NDIM * NDIM];  // [b][n][m] exp(logits)
__device__ float  g_Lpart[(size_t)BATCH * 8 * NDIM];
__device__ float  g_L[(size_t)BATCH * NDIM];          // 1 / rowsum

__device__ __forceinline__ uint32_t smem_u32(const void* p) {
    uint32_t a;
    asm("{ .reg .u64 t; cvta.to.shared.u64 t, %1; cvt.u32.u64 %0, t; }" : "=r"(a) : "l"(p));
    return a;
}
__device__ __forceinline__ void cpa16(uint32_t dst, const void* src) {
    asm volatile("cp.async.cg.shared.global [%0], [%1], 16;" :: "r"(dst), "l"(src));
}
#define CP_COMMIT() asm volatile("cp.async.commit_group;" ::: "memory")
#define CP_WAIT2()  asm volatile("cp.async.wait_group 2;" ::: "memory")

#define LDSM_X4(r0, r1, r2, r3, addr) \
    asm volatile("ldmatrix.sync.aligned.m8n8.x4.shared.b16 {%0,%1,%2,%3}, [%4];" \
                 : "=r"(r0), "=r"(r1), "=r"(r2), "=r"(r3) : "r"(addr))

__device__ __forceinline__ void mma_f16(float* c, const uint32_t* a, const uint32_t* b) {
    asm volatile(
        "mma.sync.aligned.m16n8k16.row.col.f32.f16.f16.f32 "
        "{%0,%1,%2,%3}, {%4,%5,%6,%7}, {%8,%9}, {%0,%1,%2,%3};\n"
        : "+f"(c[0]), "+f"(c[1]), "+f"(c[2]), "+f"(c[3])
        : "r"(a[0]), "r"(a[1]), "r"(a[2]), "r"(a[3]), "r"(b[0]), "r"(b[1]));
}

// ===========================================================================
// Pre-pass 1: transpose+convert.  Qt[b][n][h]=h(Q[b][h][n]); Kt[b][m][h]=h(K+PE)
// ===========================================================================
__global__ __launch_bounds__(256)
void prep_qk(const float* __restrict__ Q, const float* __restrict__ K,
             const float* __restrict__ PE) {
    __shared__ float t[32][33];
    const int b = blockIdx.z, h0 = blockIdx.y * 32, n0 = blockIdx.x * 32;
    const int tx = threadIdx.x & 31, ty = threadIdx.x >> 5;
    const size_t ibase = (size_t)b * HDIM * NDIM;
    const size_t obase = (size_t)b * NDIM * HDIM;

#pragma unroll
    for (int j = 0; j < 4; j++)
        t[ty + j * 8][tx] = Q[ibase + (size_t)(h0 + ty + j * 8) * NDIM + n0 + tx];
    __syncthreads();
#pragma unroll
    for (int j = 0; j < 4; j++)
        g_Qt[obase + (size_t)(n0 + ty + j * 8) * HDIM + h0 + tx] =
            __float2half_rn(t[tx][ty + j * 8]);
    __syncthreads();
#pragma unroll
    for (int j = 0; j < 4; j++) {
        const size_t idx = ibase + (size_t)(h0 + ty + j * 8) * NDIM + n0 + tx;
        t[ty + j * 8][tx] = K[idx] + PE[idx];
    }
    __syncthreads();
#pragma unroll
    for (int j = 0; j < 4; j++)
        g_Kt[obase + (size_t)(n0 + ty + j * 8) * HDIM + h0 + tx] =
            __float2half_rn(t[tx][ty + j * 8]);
}

// Pre-pass 2: V -> fp16 elementwise
__global__ __launch_bounds__(256)
void conv_v(const float* __restrict__ V) {
    const size_t i = ((size_t)blockIdx.x * 256 + threadIdx.x) * 4;
    float4 v = *(const float4*)(V + i);
    __half2 a = __floats2half2_rn(v.x, v.y);
    __half2 b = __floats2half2_rn(v.z, v.w);
    *(uint2*)(g_Vh + i) = make_uint2(*(uint32_t*)&a, *(uint32_t*)&b);
}

// ===========================================================================
// Warp tile 64(A-rows) x 32(B-rows). Per ks: 4 LDSM.x4 (A) + 2 LDSM.x4 (B)
// + 16 HMMA. acc[4][4][4] = 64 regs.
// ===========================================================================
__device__ __forceinline__ void mma_chunk(float acc[4][4][4], uint32_t stA, uint32_t stB,
                                          int wa, int wb, int lane) {
    const uint32_t aoff = stA + ((uint32_t)(wa + (lane & 15)) * PITCH + ((lane >> 4) * 8)) * 2;
    const uint32_t boff = stB + ((uint32_t)(wb + ((lane & 7) | ((lane & 16) >> 1))) * PITCH
                                 + (((lane >> 3) & 1) * 8)) * 2;
#pragma unroll
    for (int ks = 0; ks < 2; ks++) {
        uint32_t a[4][4], bb[4][2];
        const uint32_t kb = ks * 32;   // 16 halfs = 32 bytes
#pragma unroll
        for (int mf = 0; mf < 4; mf++)
            LDSM_X4(a[mf][0], a[mf][1], a[mf][2], a[mf][3],
                    aoff + kb + mf * (16 * PITCH * 2));
#pragma unroll
        for (int n2 = 0; n2 < 2; n2++)
            LDSM_X4(bb[2 * n2][0], bb[2 * n2][1], bb[2 * n2 + 1][0], bb[2 * n2 + 1][1],
                    boff + kb + n2 * (16 * PITCH * 2));
#pragma unroll
        for (int mf = 0; mf < 4; mf++)
#pragma unroll
            for (int nf = 0; nf < 4; nf++)
                mma_f16(acc[mf][nf], a[mf], bb[nf]);
    }
}

// ===========================================================================
// GEMM1: S[n][m] = sum_h Qt[n][h]*Kt[m][h]. CTA 128(n) x 256(m), 16 warps as
// 2(n) x 8(m), warp tile 64x32. 4-stage cp.async pipeline, KC=32.
// ===========================================================================
__global__ __launch_bounds__(NTHREADS)
void gemm1_k() {
    extern __shared__ __half S[];
    const int b = blockIdx.z, m0 = blockIdx.x * 256, n0 = blockIdx.y * 128;
    const int tid = threadIdx.x, lane = tid & 31, w = tid >> 5;
    const int gid = lane >> 2, tig = lane & 3;
    const int wn = (w & 1) * 64;    // n offset (A rows)
    const int wm = (w >> 1) * 32;   // m offset (B rows)

    const __half* Qb = g_Qt + (size_t)b * NDIM * HDIM + (size_t)n0 * HDIM;
    const __half* Kb = g_Kt + (size_t)b * NDIM * HDIM + (size_t)m0 * HDIM;
    const uint32_t sbase = smem_u32(S);

    float acc[4][4][4];
#pragma unroll
    for (int i = 0; i < 4; i++)
#pragma unroll
        for (int j = 0; j < 4; j++)
#pragma unroll
            for (int r = 0; r < 4; r++) acc[i][j][r] = 0.f;

    auto fill = [&](int c, int stg) {
        const int hc = c * KC;
        const uint32_t dA = sbase + stg * STAGE * 2;
        const uint32_t dB = dA + STAGE_A * 2;
        {   // A: 128 rows x 4 units = 512 ops, 1 per thread
            const int row = tid >> 2, u = tid & 3;
            cpa16(dA + (row * PITCH + u * 8) * 2, Qb + (size_t)row * HDIM + hc + u * 8);
        }
#pragma unroll
        for (int i = 0; i < 2; i++) {   // B: 256 rows x 4 units = 1024 ops
            const int idx = i * NTHREADS + tid, row = idx >> 2, u = idx & 3;
            cpa16(dB + (row * PITCH + u * 8) * 2, Kb + (size_t)row * HDIM + hc + u * 8);
        }
        CP_COMMIT();
    };

    const int NC = HDIM / KC;   // 24
    fill(0, 0); fill(1, 1); fill(2, 2);
#pragma unroll 1
    for (int c = 0; c < NC; c++) {
        CP_WAIT2();
        __syncthreads();
        if (c + 3 < NC) fill(c + 3, (c + 3) & 3); else CP_COMMIT();
        const uint32_t stA = sbase + (c & 3) * STAGE * 2;
        mma_chunk(acc, stA, stA + STAGE_A * 2, wn, wm, lane);
    }
    __syncthreads();

    // Epilogue: round to fp16, store E, rowsum of rounded values.
    const float scale = 0.03608439182435161f;   // 1/sqrt(768)
    __half* Eb = g_Eh + (size_t)b * NDIM * NDIM;
    float* Lred = (float*)(S + 4 * STAGE);      // [8][128]
#pragma unroll
    for (int mf = 0; mf < 4; mf++) {
        float rs0 = 0.f, rs1 = 0.f;
#pragma unroll
        for (int nf = 0; nf < 4; nf++) {
            __half2 h01 = __floats2half2_rn(__expf(acc[mf][nf][0] * scale),
                                            __expf(acc[mf][nf][1] * scale));
            __half2 h23 = __floats2half2_rn(__expf(acc[mf][nf][2] * scale),
                                            __expf(acc[mf][nf][3] * scale));
            float2 f01 = __half22float2(h01);
            float2 f23 = __half22float2(h23);
            rs0 += f01.x + f01.y;
            rs1 += f23.x + f23.y;
            const int row = n0 + wn + mf * 16 + gid;
            const int col = m0 + wm + nf * 8 + tig * 2;
            *(__half2*)(Eb + (size_t)row * NDIM + col)       = h01;
            *(__half2*)(Eb + (size_t)(row + 8) * NDIM + col) = h23;
        }
        rs0 += __shfl_xor_sync(0xffffffffu, rs0, 1);
        rs0 += __shfl_xor_sync(0xffffffffu, rs0, 2);
        rs1 += __shfl_xor_sync(0xffffffffu, rs1, 1);
        rs1 += __shfl_xor_sync(0xffffffffu, rs1, 2);
        if (tig == 0) {
            Lred[(w >> 1) * 128 + wn + mf * 16 + gid]     = rs0;
            Lred[(w >> 1) * 128 + wn + mf * 16 + gid + 8] = rs1;
        }
    }
    __syncthreads();
    if (tid < 128) {
        float s = 0.f;
#pragma unroll
        for (int j = 0; j < 8; j++) s += Lred[j * 128 + tid];
        g_Lpart[((size_t)b * 8 + blockIdx.x) * NDIM + n0 + tid] = s;
    }
}

// ===========================================================================
__global__ void rowsum_k() {
    const int t = blockIdx.x * blockDim.x + threadIdx.x;
    const int b = t >> 11, n = t & 2047;
    float s = 0.f;
#pragma unroll
    for (int j = 0; j < 8; j++)
        s += g_Lpart[((size_t)b * 8 + j) * NDIM + n];
    g_L[(size_t)b * NDIM + n] = 1.0f / s;
}

// ===========================================================================
// GEMM2: O[h][n] = (sum_m Vh[h][m]*Eh[n][m]) * Linv[n]. CTA 128(h) x 256(n),
// 16 warps as 2(h) x 8(n), warp tile 64x32.
// ===========================================================================
__global__ __launch_bounds__(NTHREADS)
void gemm2_k(float* __restrict__ out) {
    extern __shared__ __half S[];
    const int b = blockIdx.z, n0 = blockIdx.x * 256, h0 = blockIdx.y * 128;
    const int tid = threadIdx.x, lane = tid & 31, w = tid >> 5;
    const int gid = lane >> 2, tig = lane & 3;
    const int wh = (w & 1) * 64;    // h offset (A rows)
    const int wn = (w >> 1) * 32;   // n offset (B rows)

    const __half* Vb = g_Vh + (size_t)b * HDIM * NDIM + (size_t)h0 * NDIM;
    const __half* Eb = g_Eh + (size_t)b * NDIM * NDIM + (size_t)n0 * NDIM;
    const uint32_t sbase = smem_u32(S);

    float acc[4][4][4];
#pragma unroll
    for (int i = 0; i < 4; i++)
#pragma unroll
        for (int j = 0; j < 4; j++)
#pragma unroll
            for (int r = 0; r < 4; r++) acc[i][j][r] = 0.f;

    auto fill = [&](int c, int stg) {
        const int mc = c * KC;
        const uint32_t dA = sbase + stg * STAGE * 2;
        const uint32_t dB = dA + STAGE_A * 2;
        {
            const int row = tid >> 2, u = tid & 3;
            cpa16(dA + (row * PITCH + u * 8) * 2, Vb + (size_t)row * NDIM + mc + u * 8);
        }
#pragma unroll
        for (int i = 0; i < 2; i++) {
            const int idx = i * NTHREADS + tid, row = idx >> 2, u = idx & 3;
            cpa16(dB + (row * PITCH + u * 8) * 2, Eb + (size_t)row * NDIM + mc + u * 8);
        }
        CP_COMMIT();
    };

    const int NC = NDIM / KC;   // 64
    fill(0, 0); fill(1, 1); fill(2, 2);
#pragma unroll 1
    for (int c = 0; c < NC; c++) {
        CP_WAIT2();
        __syncthreads();
        if (c + 3 < NC) fill(c + 3, (c + 3) & 3); else CP_COMMIT();
        const uint32_t stA = sbase + (c & 3) * STAGE * 2;
        mma_chunk(acc, stA, stA + STAGE_A * 2, wh, wn, lane);
    }

    // Epilogue: multiply by 1/L[n], store fp32
    const float* Li = g_L + (size_t)b * NDIM;
#pragma unroll
    for (int nf = 0; nf < 4; nf++) {
        const int col = n0 + wn + nf * 8 + tig * 2;
        const float iv0 = Li[col], iv1 = Li[col + 1];
#pragma unroll
        for (int mf = 0; mf < 4; mf++) {
            const int row = h0 + wh + mf * 16 + gid;
            *(float2*)(out + (size_t)(b * HDIM + row) * NDIM + col) =
                make_float2(acc[mf][nf][0] * iv0, acc[mf][nf][1] * iv1);
            *(float2*)(out + (size_t)(b * HDIM + row + 8) * NDIM + col) =
                make_float2(acc[mf][nf][2] * iv0, acc[mf][nf][3] * iv1);
        }
    }
}

// ===========================================================================
extern "C" void kernel_launch(void* const* d_in, const int* in_sizes, int n_in,
                              void* d_out, int out_size) {
    const float* q  = (const float*)d_in[0];
    const float* k  = (const float*)d_in[1];
    const float* v  = (const float*)d_in[2];
    const float* pe = (const float*)d_in[3];
    float* out = (float*)d_out;

    cudaFuncSetAttribute(gemm1_k, cudaFuncAttributeMaxDynamicSharedMemorySize, SMEM_BYTES);
    cudaFuncSetAttribute(gemm2_k, cudaFuncAttributeMaxDynamicSharedMemorySize, SMEM_BYTES);

    prep_qk<<<dim3(NDIM / 32, HDIM / 32, BATCH), 256>>>(q, k, pe);
    conv_v<<<(BATCH * HDIM * NDIM) / 1024, 256>>>(v);
    gemm1_k<<<dim3(8, 16, BATCH), NTHREADS, SMEM_BYTES>>>();
    rowsum_k<<<(BATCH * NDIM) / 256, 256>>>();
    gemm2_k<<<dim3(8, 6, BATCH), NTHREADS, SMEM_BYTES>>>(out);
}

// round 11
// speedup vs baseline: 2.0687x; 1.0069x over previous
#include <cuda_runtime.h>
#include <cuda_fp16.h>
#include <math.h>
#include <stdint.h>

#define BATCH 16
#define HDIM  768
#define NDIM  2048
#define KC    32            // k elements per chunk (fp16)
#define PITCH 40            // smem row pitch in halfs (80B, bank-bijective + LDSM-clean)
#define STAGE_A (128 * PITCH)
#define STAGE_B (256 * PITCH)
#define STAGE   (STAGE_A + STAGE_B)          // halfs per stage (15360 = 30720B)
#define NTHREADS 512
#define SMEM_BYTES (4 * STAGE * 2 + 4096)    // 4 stages + Lred (8*128 floats)

// Scratch (allocation-free rule: __device__ globals)
__device__ __half g_Qt[(size_t)BATCH * NDIM * HDIM];  // [b][n][h]
__device__ __half g_Kt[(size_t)BATCH * NDIM * HDIM];  // [b][m][h] = fp16(K+PE)
__device__ __half g_Vh[(size_t)BATCH * HDIM * NDIM];  // [b][h][m]
__device__ __half g_Eh[(size_t)BATCH * NDIM * NDIM];  // [b][n][m] exp(logits)
__device__ float  g_Lpart[(size_t)BATCH * 8 * NDIM];
__device__ float  g_L[(size_t)BATCH * NDIM];          // 1 / rowsum

__device__ __forceinline__ uint32_t smem_u32(const void* p) {
    uint32_t a;
    asm("{ .reg .u64 t; cvta.to.shared.u64 t, %1; cvt.u32.u64 %0, t; }" : "=r"(a) : "l"(p));
    return a;
}
__device__ __forceinline__ void cpa16(uint32_t dst, const void* src) {
    asm volatile("cp.async.cg.shared.global [%0], [%1], 16;" :: "r"(dst), "l"(src));
}
#define CP_COMMIT() asm volatile("cp.async.commit_group;" ::: "memory")
#define CP_WAIT2()  asm volatile("cp.async.wait_group 2;" ::: "memory")

#define LDSM_X4(r0, r1, r2, r3, addr) \
    asm volatile("ldmatrix.sync.aligned.m8n8.x4.shared.b16 {%0,%1,%2,%3}, [%4];" \
                 : "=r"(r0), "=r"(r1), "=r"(r2), "=r"(r3) : "r"(addr))

__device__ __forceinline__ void mma_f16(float* c, const uint32_t* a, const uint32_t* b) {
    asm volatile(
        "mma.sync.aligned.m16n8k16.row.col.f32.f16.f16.f32 "
        "{%0,%1,%2,%3}, {%4,%5,%6,%7}, {%8,%9}, {%0,%1,%2,%3};\n"
        : "+f"(c[0]), "+f"(c[1]), "+f"(c[2]), "+f"(c[3])
        : "r"(a[0]), "r"(a[1]), "r"(a[2]), "r"(a[3]), "r"(b[0]), "r"(b[1]));
}

// ===========================================================================
// Pre-pass 1: transpose+convert, 64x64 tiles.
// Qt[b][n][h] = h(Q[b][h][n]);  Kt[b][m][h] = h(K[b][h][m] + PE[b][h][m])
// Global loads float4 (coalesced); smem stores SCALAR (65-pad is only 4B
// aligned for odd rows); smem reads down columns (bank (row+sn)%32, clean);
// global stores uint4 = 8 halfs along h (coalesced, 16B aligned).
// ===========================================================================
__global__ __launch_bounds__(512)
void prep_qk(const float* __restrict__ Q, const float* __restrict__ K,
             const float* __restrict__ PE) {
    __shared__ float t[64][65];
    const int b = blockIdx.z, h0 = blockIdx.y * 64, n0 = blockIdx.x * 64;
    const int tid = threadIdx.x;
    const size_t ibase = (size_t)b * HDIM * NDIM;
    const size_t obase = (size_t)b * NDIM * HDIM;

    const int sn = tid >> 3, shb = (tid & 7) * 8;   // store: n-row, h-base

    // ---- Q ----
#pragma unroll
    for (int i = 0; i < 2; i++) {
        const int idx = i * 512 + tid, row = idx >> 4, c4 = (idx & 15) * 4;
        const float4 v = *(const float4*)(Q + ibase + (size_t)(h0 + row) * NDIM + n0 + c4);
        t[row][c4] = v.x; t[row][c4 + 1] = v.y; t[row][c4 + 2] = v.z; t[row][c4 + 3] = v.w;
    }
    __syncthreads();
    {
        __align__(16) __half2 o[4];
#pragma unroll
        for (int j = 0; j < 4; j++)
            o[j] = __floats2half2_rn(t[shb + 2 * j][sn], t[shb + 2 * j + 1][sn]);
        *(uint4*)(g_Qt + obase + (size_t)(n0 + sn) * HDIM + h0 + shb) = *(uint4*)o;
    }
    __syncthreads();

    // ---- K + PE ----
#pragma unroll
    for (int i = 0; i < 2; i++) {
        const int idx = i * 512 + tid, row = idx >> 4, c4 = (idx & 15) * 4;
        const size_t g = ibase + (size_t)(h0 + row) * NDIM + n0 + c4;
        const float4 kv = *(const float4*)(K + g);
        const float4 pv = *(const float4*)(PE + g);
        t[row][c4]     = kv.x + pv.x;
        t[row][c4 + 1] = kv.y + pv.y;
        t[row][c4 + 2] = kv.z + pv.z;
        t[row][c4 + 3] = kv.w + pv.w;
    }
    __syncthreads();
    {
        __align__(16) __half2 o[4];
#pragma unroll
        for (int j = 0; j < 4; j++)
            o[j] = __floats2half2_rn(t[shb + 2 * j][sn], t[shb + 2 * j + 1][sn]);
        *(uint4*)(g_Kt + obase + (size_t)(n0 + sn) * HDIM + h0 + shb) = *(uint4*)o;
    }
}

// Pre-pass 2: V -> fp16, 8 elements/thread, 16B stores
__global__ __launch_bounds__(256)
void conv_v(const float* __restrict__ V) {
    const size_t i = ((size_t)blockIdx.x * 256 + threadIdx.x) * 8;
    const float4 v0 = *(const float4*)(V + i);
    const float4 v1 = *(const float4*)(V + i + 4);
    __align__(16) __half2 o[4];
    o[0] = __floats2half2_rn(v0.x, v0.y);
    o[1] = __floats2half2_rn(v0.z, v0.w);
    o[2] = __floats2half2_rn(v1.x, v1.y);
    o[3] = __floats2half2_rn(v1.z, v1.w);
    *(uint4*)(g_Vh + i) = *(uint4*)o;
}

// ===========================================================================
// Warp tile 64(A-rows) x 32(B-rows). Per ks: 4 LDSM.x4 (A) + 2 LDSM.x4 (B)
// + 16 HMMA. acc[4][4][4] = 64 regs.
// ===========================================================================
__device__ __forceinline__ void mma_chunk(float acc[4][4][4], uint32_t stA, uint32_t stB,
                                          int wa, int wb, int lane) {
    const uint32_t aoff = stA + ((uint32_t)(wa + (lane & 15)) * PITCH + ((lane >> 4) * 8)) * 2;
    const uint32_t boff = stB + ((uint32_t)(wb + ((lane & 7) | ((lane & 16) >> 1))) * PITCH
                                 + (((lane >> 3) & 1) * 8)) * 2;
#pragma unroll
    for (int ks = 0; ks < 2; ks++) {
        uint32_t a[4][4], bb[4][2];
        const uint32_t kb = ks * 32;   // 16 halfs = 32 bytes
#pragma unroll
        for (int mf = 0; mf < 4; mf++)
            LDSM_X4(a[mf][0], a[mf][1], a[mf][2], a[mf][3],
                    aoff + kb + mf * (16 * PITCH * 2));
#pragma unroll
        for (int n2 = 0; n2 < 2; n2++)
            LDSM_X4(bb[2 * n2][0], bb[2 * n2][1], bb[2 * n2 + 1][0], bb[2 * n2 + 1][1],
                    boff + kb + n2 * (16 * PITCH * 2));
#pragma unroll
        for (int mf = 0; mf < 4; mf++)
#pragma unroll
            for (int nf = 0; nf < 4; nf++)
                mma_f16(acc[mf][nf], a[mf], bb[nf]);
    }
}

// ===========================================================================
// GEMM1: S[n][m] = sum_h Qt[n][h]*Kt[m][h]. CTA 128(n) x 256(m), 16 warps as
// 2(n) x 8(m), warp tile 64x32. 4-stage cp.async pipeline, KC=32.
// ===========================================================================
__global__ __launch_bounds__(NTHREADS)
void gemm1_k() {
    extern __shared__ __half S[];
    const int b = blockIdx.z, m0 = blockIdx.x * 256, n0 = blockIdx.y * 128;
    const int tid = threadIdx.x, lane = tid & 31, w = tid >> 5;
    const int gid = lane >> 2, tig = lane & 3;
    const int wn = (w & 1) * 64;    // n offset (A rows)
    const int wm = (w >> 1) * 32;   // m offset (B rows)

    const __half* Qb = g_Qt + (size_t)b * NDIM * HDIM + (size_t)n0 * HDIM;
    const __half* Kb = g_Kt + (size_t)b * NDIM * HDIM + (size_t)m0 * HDIM;
    const uint32_t sbase = smem_u32(S);

    float acc[4][4][4];
#pragma unroll
    for (int i = 0; i < 4; i++)
#pragma unroll
        for (int j = 0; j < 4; j++)
#pragma unroll
            for (int r = 0; r < 4; r++) acc[i][j][r] = 0.f;

    auto fill = [&](int c, int stg) {
        const int hc = c * KC;
        const uint32_t dA = sbase + stg * STAGE * 2;
        const uint32_t dB = dA + STAGE_A * 2;
        {   // A: 128 rows x 4 units = 512 ops, 1 per thread
            const int row = tid >> 2, u = tid & 3;
            cpa16(dA + (row * PITCH + u * 8) * 2, Qb + (size_t)row * HDIM + hc + u * 8);
        }
#pragma unroll
        for (int i = 0; i < 2; i++) {   // B: 256 rows x 4 units = 1024 ops
            const int idx = i * NTHREADS + tid, row = idx >> 2, u = idx & 3;
            cpa16(dB + (row * PITCH + u * 8) * 2, Kb + (size_t)row * HDIM + hc + u * 8);
        }
        CP_COMMIT();
    };

    const int NC = HDIM / KC;   // 24
    fill(0, 0); fill(1, 1); fill(2, 2);
#pragma unroll 1
    for (int c = 0; c < NC; c++) {
        CP_WAIT2();
        __syncthreads();
        if (c + 3 < NC) fill(c + 3, (c + 3) & 3); else CP_COMMIT();
        const uint32_t stA = sbase + (c & 3) * STAGE * 2;
        mma_chunk(acc, stA, stA + STAGE_A * 2, wn, wm, lane);
    }
    __syncthreads();

    // Epilogue: round to fp16, store E, rowsum of rounded values.
    const float scale = 0.03608439182435161f;   // 1/sqrt(768)
    __half* Eb = g_Eh + (size_t)b * NDIM * NDIM;
    float* Lred = (float*)(S + 4 * STAGE);      // [8][128]
#pragma unroll
    for (int mf = 0; mf < 4; mf++) {
        float rs0 = 0.f, rs1 = 0.f;
#pragma unroll
        for (int nf = 0; nf < 4; nf++) {
            __half2 h01 = __floats2half2_rn(__expf(acc[mf][nf][0] * scale),
                                            __expf(acc[mf][nf][1] * scale));
            __half2 h23 = __floats2half2_rn(__expf(acc[mf][nf][2] * scale),
                                            __expf(acc[mf][nf][3] * scale));
            float2 f01 = __half22float2(h01);
            float2 f23 = __half22float2(h23);
            rs0 += f01.x + f01.y;
            rs1 += f23.x + f23.y;
            const int row = n0 + wn + mf * 16 + gid;
            const int col = m0 + wm + nf * 8 + tig * 2;
            *(__half2*)(Eb + (size_t)row * NDIM + col)       = h01;
            *(__half2*)(Eb + (size_t)(row + 8) * NDIM + col) = h23;
        }
        rs0 += __shfl_xor_sync(0xffffffffu, rs0, 1);
        rs0 += __shfl_xor_sync(0xffffffffu, rs0, 2);
        rs1 += __shfl_xor_sync(0xffffffffu, rs1, 1);
        rs1 += __shfl_xor_sync(0xffffffffu, rs1, 2);
        if (tig == 0) {
            Lred[(w >> 1) * 128 + wn + mf * 16 + gid]     = rs0;
            Lred[(w >> 1) * 128 + wn + mf * 16 + gid + 8] = rs1;
        }
    }
    __syncthreads();
    if (tid < 128) {
        float s = 0.f;
#pragma unroll
        for (int j = 0; j < 8; j++) s += Lred[j * 128 + tid];
        g_Lpart[((size_t)b * 8 + blockIdx.x) * NDIM + n0 + tid] = s;
    }
}

// ===========================================================================
__global__ void rowsum_k() {
    const int t = blockIdx.x * blockDim.x + threadIdx.x;
    const int b = t >> 11, n = t & 2047;
    float s = 0.f;
#pragma unroll
    for (int j = 0; j < 8; j++)
        s += g_Lpart[((size_t)b * 8 + j) * NDIM + n];
    g_L[(size_t)b * NDIM + n] = 1.0f / s;
}

// ===========================================================================
// GEMM2: O[h][n] = (sum_m Vh[h][m]*Eh[n][m]) * Linv[n]. CTA 128(h) x 256(n),
// 16 warps as 2(h) x 8(n), warp tile 64x32.
// ===========================================================================
__global__ __launch_bounds__(NTHREADS)
void gemm2_k(float* __restrict__ out) {
    extern __shared__ __half S[];
    const int b = blockIdx.z, n0 = blockIdx.x * 256, h0 = blockIdx.y * 128;
    const int tid = threadIdx.x, lane = tid & 31, w = tid >> 5;
    const int gid = lane >> 2, tig = lane & 3;
    const int wh = (w & 1) * 64;    // h offset (A rows)
    const int wn = (w >> 1) * 32;   // n offset (B rows)

    const __half* Vb = g_Vh + (size_t)b * HDIM * NDIM + (size_t)h0 * NDIM;
    const __half* Eb = g_Eh + (size_t)b * NDIM * NDIM + (size_t)n0 * NDIM;
    const uint32_t sbase = smem_u32(S);

    float acc[4][4][4];
#pragma unroll
    for (int i = 0; i < 4; i++)
#pragma unroll
        for (int j = 0; j < 4; j++)
#pragma unroll
            for (int r = 0; r < 4; r++) acc[i][j][r] = 0.f;

    auto fill = [&](int c, int stg) {
        const int mc = c * KC;
        const uint32_t dA = sbase + stg * STAGE * 2;
        const uint32_t dB = dA + STAGE_A * 2;
        {
            const int row = tid >> 2, u = tid & 3;
            cpa16(dA + (row * PITCH + u * 8) * 2, Vb + (size_t)row * NDIM + mc + u * 8);
        }
#pragma unroll
        for (int i = 0; i < 2; i++) {
            const int idx = i * NTHREADS + tid, row = idx >> 2, u = idx & 3;
            cpa16(dB + (row * PITCH + u * 8) * 2, Eb + (size_t)row * NDIM + mc + u * 8);
        }
        CP_COMMIT();
    };

    const int NC = NDIM / KC;   // 64
    fill(0, 0); fill(1, 1); fill(2, 2);
#pragma unroll 1
    for (int c = 0; c < NC; c++) {
        CP_WAIT2();
        __syncthreads();
        if (c + 3 < NC) fill(c + 3, (c + 3) & 3); else CP_COMMIT();
        const uint32_t stA = sbase + (c & 3) * STAGE * 2;
        mma_chunk(acc, stA, stA + STAGE_A * 2, wh, wn, lane);
    }

    // Epilogue: multiply by 1/L[n], store fp32
    const float* Li = g_L + (size_t)b * NDIM;
#pragma unroll
    for (int nf = 0; nf < 4; nf++) {
        const int col = n0 + wn + nf * 8 + tig * 2;
        const float iv0 = Li[col], iv1 = Li[col + 1];
#pragma unroll
        for (int mf = 0; mf < 4; mf++) {
            const int row = h0 + wh + mf * 16 + gid;
            *(float2*)(out + (size_t)(b * HDIM + row) * NDIM + col) =
                make_float2(acc[mf][nf][0] * iv0, acc[mf][nf][1] * iv1);
            *(float2*)(out + (size_t)(b * HDIM + row + 8) * NDIM + col) =
                make_float2(acc[mf][nf][2] * iv0, acc[mf][nf][3] * iv1);
        }
    }
}

// ===========================================================================
extern "C" void kernel_launch(void* const* d_in, const int* in_sizes, int n_in,
                              void* d_out, int out_size) {
    const float* q  = (const float*)d_in[0];
    const float* k  = (const float*)d_in[1];
    const float* v  = (const float*)d_in[2];
    const float* pe = (const float*)d_in[3];
    float* out = (float*)d_out;

    cudaFuncSetAttribute(gemm1_k, cudaFuncAttributeMaxDynamicSharedMemorySize, SMEM_BYTES);
    cudaFuncSetAttribute(gemm2_k, cudaFuncAttributeMaxDynamicSharedMemorySize, SMEM_BYTES);

    prep_qk<<<dim3(NDIM / 64, HDIM / 64, BATCH), 512>>>(q, k, pe);
    conv_v<<<(BATCH * HDIM * NDIM) / 2048, 256>>>(v);
    gemm1_k<<<dim3(8, 16, BATCH), NTHREADS, SMEM_BYTES>>>();
    rowsum_k<<<(BATCH * NDIM) / 256, 256>>>();
    gemm2_k<<<dim3(8, 6, BATCH), NTHREADS, SMEM_BYTES>>>(out);
}

// round 12
// speedup vs baseline: 2.2946x; 1.1092x over previous
#include <cuda_runtime.h>
#include <cuda_fp16.h>
#include <math.h>
#include <stdint.h>

#define BATCH 16
#define HDIM  768
#define NDIM  2048
#define KC    64            // k elements per chunk (fp16)
#define PITCH 72            // smem row pitch in halfs (144B, LDSM/cp.async conflict-free)
#define STAGE_A (128 * PITCH)
#define STAGE_B (256 * PITCH)
#define STAGE   (STAGE_A + STAGE_B)          // halfs per stage (27648 = 55296B)
#define NSTAGE  3
#define NTHREADS 512
#define SMEM_BYTES (NSTAGE * STAGE * 2 + 4096)   // 3 stages + Lred (8*128 floats)

// Scratch (allocation-free rule: __device__ globals)
__device__ __half g_Qt[(size_t)BATCH * NDIM * HDIM];  // [b][n][h]
__device__ __half g_Kt[(size_t)BATCH * NDIM * HDIM];  // [b][m][h] = fp16(K+PE)
__device__ __half g_Vh[(size_t)BATCH * HDIM * NDIM];  // [b][h][m]
__device__ __half g_Eh[(size_t)BATCH * NDIM * NDIM];  // [b][n][m] exp(logits)
__device__ float  g_Lpart[(size_t)BATCH * 8 * NDIM];
__device__ float  g_L[(size_t)BATCH * NDIM];          // 1 / rowsum

__device__ __forceinline__ uint32_t smem_u32(const void* p) {
    uint32_t a;
    asm("{ .reg .u64 t; cvta.to.shared.u64 t, %1; cvt.u32.u64 %0, t; }" : "=r"(a) : "l"(p));
    return a;
}
__device__ __forceinline__ void cpa16(uint32_t dst, const void* src) {
    asm volatile("cp.async.cg.shared.global [%0], [%1], 16;" :: "r"(dst), "l"(src));
}
#define CP_COMMIT() asm volatile("cp.async.commit_group;" ::: "memory")
#define CP_WAIT1()  asm volatile("cp.async.wait_group 1;" ::: "memory")

#define LDSM_X4(r0, r1, r2, r3, addr) \
    asm volatile("ldmatrix.sync.aligned.m8n8.x4.shared.b16 {%0,%1,%2,%3}, [%4];" \
                 : "=r"(r0), "=r"(r1), "=r"(r2), "=r"(r3) : "r"(addr))

__device__ __forceinline__ void mma_f16(float* c, const uint32_t* a, const uint32_t* b) {
    asm volatile(
        "mma.sync.aligned.m16n8k16.row.col.f32.f16.f16.f32 "
        "{%0,%1,%2,%3}, {%4,%5,%6,%7}, {%8,%9}, {%0,%1,%2,%3};\n"
        : "+f"(c[0]), "+f"(c[1]), "+f"(c[2]), "+f"(c[3])
        : "r"(a[0]), "r"(a[1]), "r"(a[2]), "r"(a[3]), "r"(b[0]), "r"(b[1]));
}

// ===========================================================================
// Pre-pass 1: transpose+convert, 64x64 tiles.
// Qt[b][n][h] = h(Q[b][h][n]);  Kt[b][m][h] = h(K[b][h][m] + PE[b][h][m])
// ===========================================================================
__global__ __launch_bounds__(512)
void prep_qk(const float* __restrict__ Q, const float* __restrict__ K,
             const float* __restrict__ PE) {
    __shared__ float t[64][65];
    const int b = blockIdx.z, h0 = blockIdx.y * 64, n0 = blockIdx.x * 64;
    const int tid = threadIdx.x;
    const size_t ibase = (size_t)b * HDIM * NDIM;
    const size_t obase = (size_t)b * NDIM * HDIM;

    const int sn = tid >> 3, shb = (tid & 7) * 8;   // store: n-row, h-base

    // ---- Q ----
#pragma unroll
    for (int i = 0; i < 2; i++) {
        const int idx = i * 512 + tid, row = idx >> 4, c4 = (idx & 15) * 4;
        const float4 v = *(const float4*)(Q + ibase + (size_t)(h0 + row) * NDIM + n0 + c4);
        t[row][c4] = v.x; t[row][c4 + 1] = v.y; t[row][c4 + 2] = v.z; t[row][c4 + 3] = v.w;
    }
    __syncthreads();
    {
        __align__(16) __half2 o[4];
#pragma unroll
        for (int j = 0; j < 4; j++)
            o[j] = __floats2half2_rn(t[shb + 2 * j][sn], t[shb + 2 * j + 1][sn]);
        *(uint4*)(g_Qt + obase + (size_t)(n0 + sn) * HDIM + h0 + shb) = *(uint4*)o;
    }
    __syncthreads();

    // ---- K + PE ----
#pragma unroll
    for (int i = 0; i < 2; i++) {
        const int idx = i * 512 + tid, row = idx >> 4, c4 = (idx & 15) * 4;
        const size_t g = ibase + (size_t)(h0 + row) * NDIM + n0 + c4;
        const float4 kv = *(const float4*)(K + g);
        const float4 pv = *(const float4*)(PE + g);
        t[row][c4]     = kv.x + pv.x;
        t[row][c4 + 1] = kv.y + pv.y;
        t[row][c4 + 2] = kv.z + pv.z;
        t[row][c4 + 3] = kv.w + pv.w;
    }
    __syncthreads();
    {
        __align__(16) __half2 o[4];
#pragma unroll
        for (int j = 0; j < 4; j++)
            o[j] = __floats2half2_rn(t[shb + 2 * j][sn], t[shb + 2 * j + 1][sn]);
        *(uint4*)(g_Kt + obase + (size_t)(n0 + sn) * HDIM + h0 + shb) = *(uint4*)o;
    }
}

// Pre-pass 2: V -> fp16, 8 elements/thread, 16B stores
__global__ __launch_bounds__(256)
void conv_v(const float* __restrict__ V) {
    const size_t i = ((size_t)blockIdx.x * 256 + threadIdx.x) * 8;
    const float4 v0 = *(const float4*)(V + i);
    const float4 v1 = *(const float4*)(V + i + 4);
    __align__(16) __half2 o[4];
    o[0] = __floats2half2_rn(v0.x, v0.y);
    o[1] = __floats2half2_rn(v0.z, v0.w);
    o[2] = __floats2half2_rn(v1.x, v1.y);
    o[3] = __floats2half2_rn(v1.z, v1.w);
    *(uint4*)(g_Vh + i) = *(uint4*)o;
}

// ===========================================================================
// Warp tile 64(A-rows) x 32(B-rows). Per chunk (KC=64): 4 ks iterations of
// 4 LDSM.x4 (A) + 2 LDSM.x4 (B) + 16 HMMA. acc[4][4][4] = 64 regs.
// ===========================================================================
__device__ __forceinline__ void mma_chunk(float acc[4][4][4], uint32_t stA, uint32_t stB,
                                          int wa, int wb, int lane) {
    const uint32_t aoff = stA + ((uint32_t)(wa + (lane & 15)) * PITCH + ((lane >> 4) * 8)) * 2;
    const uint32_t boff = stB + ((uint32_t)(wb + ((lane & 7) | ((lane & 16) >> 1))) * PITCH
                                 + (((lane >> 3) & 1) * 8)) * 2;
#pragma unroll
    for (int ks = 0; ks < 4; ks++) {
        uint32_t a[4][4], bb[4][2];
        const uint32_t kb = ks * 32;   // 16 halfs = 32 bytes per ks
#pragma unroll
        for (int mf = 0; mf < 4; mf++)
            LDSM_X4(a[mf][0], a[mf][1], a[mf][2], a[mf][3],
                    aoff + kb + mf * (16 * PITCH * 2));
#pragma unroll
        for (int n2 = 0; n2 < 2; n2++)
            LDSM_X4(bb[2 * n2][0], bb[2 * n2][1], bb[2 * n2 + 1][0], bb[2 * n2 + 1][1],
                    boff + kb + n2 * (16 * PITCH * 2));
#pragma unroll
        for (int mf = 0; mf < 4; mf++)
#pragma unroll
            for (int nf = 0; nf < 4; nf++)
                mma_f16(acc[mf][nf], a[mf], bb[nf]);
    }
}

// ===========================================================================
// GEMM1: S[n][m] = sum_h Qt[n][h]*Kt[m][h]. CTA 128(n) x 256(m), 16 warps as
// 2(n) x 8(m), warp tile 64x32. 3-stage cp.async pipeline, KC=64.
// ===========================================================================
__global__ __launch_bounds__(NTHREADS)
void gemm1_k() {
    extern __shared__ __half S[];
    const int b = blockIdx.z, m0 = blockIdx.x * 256, n0 = blockIdx.y * 128;
    const int tid = threadIdx.x, lane = tid & 31, w = tid >> 5;
    const int gid = lane >> 2, tig = lane & 3;
    const int wn = (w & 1) * 64;    // n offset (A rows)
    const int wm = (w >> 1) * 32;   // m offset (B rows)

    const __half* Qb = g_Qt + (size_t)b * NDIM * HDIM + (size_t)n0 * HDIM;
    const __half* Kb = g_Kt + (size_t)b * NDIM * HDIM + (size_t)m0 * HDIM;
    const uint32_t sbase = smem_u32(S);

    float acc[4][4][4];
#pragma unroll
    for (int i = 0; i < 4; i++)
#pragma unroll
        for (int j = 0; j < 4; j++)
#pragma unroll
            for (int r = 0; r < 4; r++) acc[i][j][r] = 0.f;

    auto fill = [&](int c, int stg) {
        const int hc = c * KC;
        const uint32_t dA = sbase + stg * STAGE * 2;
        const uint32_t dB = dA + STAGE_A * 2;
#pragma unroll
        for (int i = 0; i < 2; i++) {   // A: 128 rows x 8 units = 1024 ops
            const int idx = i * NTHREADS + tid, row = idx >> 3, u = idx & 7;
            cpa16(dA + (row * PITCH + u * 8) * 2, Qb + (size_t)row * HDIM + hc + u * 8);
        }
#pragma unroll
        for (int i = 0; i < 4; i++) {   // B: 256 rows x 8 units = 2048 ops
            const int idx = i * NTHREADS + tid, row = idx >> 3, u = idx & 7;
            cpa16(dB + (row * PITCH + u * 8) * 2, Kb + (size_t)row * HDIM + hc + u * 8);
        }
        CP_COMMIT();
    };

    const int NC = HDIM / KC;   // 12
    fill(0, 0); fill(1, 1);
    int stg = 0;
#pragma unroll 1
    for (int c = 0; c < NC; c++) {
        CP_WAIT1();
        __syncthreads();
        if (c + 2 < NC) {
            int s2 = stg + 2; if (s2 >= NSTAGE) s2 -= NSTAGE;
            fill(c + 2, s2);
        } else CP_COMMIT();
        const uint32_t stA = sbase + stg * STAGE * 2;
        mma_chunk(acc, stA, stA + STAGE_A * 2, wn, wm, lane);
        if (++stg == NSTAGE) stg = 0;
    }
    __syncthreads();

    // Epilogue: round to fp16, store E, rowsum of rounded values.
    const float scale = 0.03608439182435161f;   // 1/sqrt(768)
    __half* Eb = g_Eh + (size_t)b * NDIM * NDIM;
    float* Lred = (float*)(S + NSTAGE * STAGE);      // [8][128]
#pragma unroll
    for (int mf = 0; mf < 4; mf++) {
        float rs0 = 0.f, rs1 = 0.f;
#pragma unroll
        for (int nf = 0; nf < 4; nf++) {
            __half2 h01 = __floats2half2_rn(__expf(acc[mf][nf][0] * scale),
                                            __expf(acc[mf][nf][1] * scale));
            __half2 h23 = __floats2half2_rn(__expf(acc[mf][nf][2] * scale),
                                            __expf(acc[mf][nf][3] * scale));
            float2 f01 = __half22float2(h01);
            float2 f23 = __half22float2(h23);
            rs0 += f01.x + f01.y;
            rs1 += f23.x + f23.y;
            const int row = n0 + wn + mf * 16 + gid;
            const int col = m0 + wm + nf * 8 + tig * 2;
            *(__half2*)(Eb + (size_t)row * NDIM + col)       = h01;
            *(__half2*)(Eb + (size_t)(row + 8) * NDIM + col) = h23;
        }
        rs0 += __shfl_xor_sync(0xffffffffu, rs0, 1);
        rs0 += __shfl_xor_sync(0xffffffffu, rs0, 2);
        rs1 += __shfl_xor_sync(0xffffffffu, rs1, 1);
        rs1 += __shfl_xor_sync(0xffffffffu, rs1, 2);
        if (tig == 0) {
            Lred[(w >> 1) * 128 + wn + mf * 16 + gid]     = rs0;
            Lred[(w >> 1) * 128 + wn + mf * 16 + gid + 8] = rs1;
        }
    }
    __syncthreads();
    if (tid < 128) {
        float s = 0.f;
#pragma unroll
        for (int j = 0; j < 8; j++) s += Lred[j * 128 + tid];
        g_Lpart[((size_t)b * 8 + blockIdx.x) * NDIM + n0 + tid] = s;
    }
}

// ===========================================================================
__global__ void rowsum_k() {
    const int t = blockIdx.x * blockDim.x + threadIdx.x;
    const int b = t >> 11, n = t & 2047;
    float s = 0.f;
#pragma unroll
    for (int j = 0; j < 8; j++)
        s += g_Lpart[((size_t)b * 8 + j) * NDIM + n];
    g_L[(size_t)b * NDIM + n] = 1.0f / s;
}

// ===========================================================================
// GEMM2: O[h][n] = (sum_m Vh[h][m]*Eh[n][m]) * Linv[n]. CTA 128(h) x 256(n),
// 16 warps as 2(h) x 8(n), warp tile 64x32. 3-stage pipeline, KC=64.
// ===========================================================================
__global__ __launch_bounds__(NTHREADS)
void gemm2_k(float* __restrict__ out) {
    extern __shared__ __half S[];
    const int b = blockIdx.z, n0 = blockIdx.x * 256, h0 = blockIdx.y * 128;
    const int tid = threadIdx.x, lane = tid & 31, w = tid >> 5;
    const int gid = lane >> 2, tig = lane & 3;
    const int wh = (w & 1) * 64;    // h offset (A rows)
    const int wn = (w >> 1) * 32;   // n offset (B rows)

    const __half* Vb = g_Vh + (size_t)b * HDIM * NDIM + (size_t)h0 * NDIM;
    const __half* Eb = g_Eh + (size_t)b * NDIM * NDIM + (size_t)n0 * NDIM;
    const uint32_t sbase = smem_u32(S);

    float acc[4][4][4];
#pragma unroll
    for (int i = 0; i < 4; i++)
#pragma unroll
        for (int j = 0; j < 4; j++)
#pragma unroll
            for (int r = 0; r < 4; r++) acc[i][j][r] = 0.f;

    auto fill = [&](int c, int stg) {
        const int mc = c * KC;
        const uint32_t dA = sbase + stg * STAGE * 2;
        const uint32_t dB = dA + STAGE_A * 2;
#pragma unroll
        for (int i = 0; i < 2; i++) {
            const int idx = i * NTHREADS + tid, row = idx >> 3, u = idx & 7;
            cpa16(dA + (row * PITCH + u * 8) * 2, Vb + (size_t)row * NDIM + mc + u * 8);
        }
#pragma unroll
        for (int i = 0; i < 4; i++) {
            const int idx = i * NTHREADS + tid, row = idx >> 3, u = idx & 7;
            cpa16(dB + (row * PITCH + u * 8) * 2, Eb + (size_t)row * NDIM + mc + u * 8);
        }
        CP_COMMIT();
    };

    const int NC = NDIM / KC;   // 32
    fill(0, 0); fill(1, 1);
    int stg = 0;
#pragma unroll 1
    for (int c = 0; c < NC; c++) {
        CP_WAIT1();
        __syncthreads();
        if (c + 2 < NC) {
            int s2 = stg + 2; if (s2 >= NSTAGE) s2 -= NSTAGE;
            fill(c + 2, s2);
        } else CP_COMMIT();
        const uint32_t stA = sbase + stg * STAGE * 2;
        mma_chunk(acc, stA, stA + STAGE_A * 2, wh, wn, lane);
        if (++stg == NSTAGE) stg = 0;
    }

    // Epilogue: multiply by 1/L[n], store fp32
    const float* Li = g_L + (size_t)b * NDIM;
#pragma unroll
    for (int nf = 0; nf < 4; nf++) {
        const int col = n0 + wn + nf * 8 + tig * 2;
        const float iv0 = Li[col], iv1 = Li[col + 1];
#pragma unroll
        for (int mf = 0; mf < 4; mf++) {
            const int row = h0 + wh + mf * 16 + gid;
            *(float2*)(out + (size_t)(b * HDIM + row) * NDIM + col) =
                make_float2(acc[mf][nf][0] * iv0, acc[mf][nf][1] * iv1);
            *(float2*)(out + (size_t)(b * HDIM + row + 8) * NDIM + col) =
                make_float2(acc[mf][nf][2] * iv0, acc[mf][nf][3] * iv1);
        }
    }
}

// ===========================================================================
extern "C" void kernel_launch(void* const* d_in, const int* in_sizes, int n_in,
                              void* d_out, int out_size) {
    const float* q  = (const float*)d_in[0];
    const float* k  = (const float*)d_in[1];
    const float* v  = (const float*)d_in[2];
    const float* pe = (const float*)d_in[3];
    float* out = (float*)d_out;

    cudaFuncSetAttribute(gemm1_k, cudaFuncAttributeMaxDynamicSharedMemorySize, SMEM_BYTES);
    cudaFuncSetAttribute(gemm2_k, cudaFuncAttributeMaxDynamicSharedMemorySize, SMEM_BYTES);

    prep_qk<<<dim3(NDIM / 64, HDIM / 64, BATCH), 512>>>(q, k, pe);
    conv_v<<<(BATCH * HDIM * NDIM) / 2048, 256>>>(v);
    gemm1_k<<<dim3(8, 16, BATCH), NTHREADS, SMEM_BYTES>>>();
    rowsum_k<<<(BATCH * NDIM) / 256, 256>>>();
    gemm2_k<<<dim3(8, 6, BATCH), NTHREADS, SMEM_BYTES>>>(out);
}

// round 13
// speedup vs baseline: 2.6348x; 1.1482x over previous
#include <cuda_runtime.h>
#include <cuda_fp16.h>
#include <math.h>
#include <stdint.h>

#define BATCH 16
#define HDIM  768
#define NDIM  2048
#define KC    64            // k elements per chunk (fp16)
#define PITCH 72            // smem row pitch in halfs (144B, LDSM/cp.async conflict-free)
#define STAGE_A (128 * PITCH)
#define STAGE_B (128 * PITCH)
#define STAGE   (STAGE_A + STAGE_B)          // halfs per stage (18432 = 36864B)
#define NSTAGE  3
#define NTHREADS 256
#define SMEM_BYTES (NSTAGE * STAGE * 2 + 2048)   // 3 stages + Lred (4*128 floats)

// Scratch (allocation-free rule: __device__ globals)
__device__ __half g_Qt[(size_t)BATCH * NDIM * HDIM];  // [b][n][h]
__device__ __half g_Kt[(size_t)BATCH * NDIM * HDIM];  // [b][m][h] = fp16(K+PE)
__device__ __half g_Vh[(size_t)BATCH * HDIM * NDIM];  // [b][h][m]
__device__ __half g_Eh[(size_t)BATCH * NDIM * NDIM];  // [b][n][m] exp(logits)
__device__ float  g_Lpart[(size_t)BATCH * 16 * NDIM];
__device__ float  g_L[(size_t)BATCH * NDIM];          // 1 / rowsum

__device__ __forceinline__ uint32_t smem_u32(const void* p) {
    uint32_t a;
    asm("{ .reg .u64 t; cvta.to.shared.u64 t, %1; cvt.u32.u64 %0, t; }" : "=r"(a) : "l"(p));
    return a;
}
__device__ __forceinline__ void cpa16(uint32_t dst, const void* src) {
    asm volatile("cp.async.cg.shared.global [%0], [%1], 16;" :: "r"(dst), "l"(src));
}
#define CP_COMMIT() asm volatile("cp.async.commit_group;" ::: "memory")
#define CP_WAIT1()  asm volatile("cp.async.wait_group 1;" ::: "memory")

#define LDSM_X4(r0, r1, r2, r3, addr) \
    asm volatile("ldmatrix.sync.aligned.m8n8.x4.shared.b16 {%0,%1,%2,%3}, [%4];" \
                 : "=r"(r0), "=r"(r1), "=r"(r2), "=r"(r3) : "r"(addr))

__device__ __forceinline__ void mma_f16(float* c, const uint32_t* a, const uint32_t* b) {
    asm volatile(
        "mma.sync.aligned.m16n8k16.row.col.f32.f16.f16.f32 "
        "{%0,%1,%2,%3}, {%4,%5,%6,%7}, {%8,%9}, {%0,%1,%2,%3};\n"
        : "+f"(c[0]), "+f"(c[1]), "+f"(c[2]), "+f"(c[3])
        : "r"(a[0]), "r"(a[1]), "r"(a[2]), "r"(a[3]), "r"(b[0]), "r"(b[1]));
}

// ===========================================================================
// Pre-pass 1: transpose+convert, 64x64 tiles.
// ===========================================================================
__global__ __launch_bounds__(512)
void prep_qk(const float* __restrict__ Q, const float* __restrict__ K,
             const float* __restrict__ PE) {
    __shared__ float t[64][65];
    const int b = blockIdx.z, h0 = blockIdx.y * 64, n0 = blockIdx.x * 64;
    const int tid = threadIdx.x;
    const size_t ibase = (size_t)b * HDIM * NDIM;
    const size_t obase = (size_t)b * NDIM * HDIM;

    const int sn = tid >> 3, shb = (tid & 7) * 8;

    // ---- Q ----
#pragma unroll
    for (int i = 0; i < 2; i++) {
        const int idx = i * 512 + tid, row = idx >> 4, c4 = (idx & 15) * 4;
        const float4 v = *(const float4*)(Q + ibase + (size_t)(h0 + row) * NDIM + n0 + c4);
        t[row][c4] = v.x; t[row][c4 + 1] = v.y; t[row][c4 + 2] = v.z; t[row][c4 + 3] = v.w;
    }
    __syncthreads();
    {
        __align__(16) __half2 o[4];
#pragma unroll
        for (int j = 0; j < 4; j++)
            o[j] = __floats2half2_rn(t[shb + 2 * j][sn], t[shb + 2 * j + 1][sn]);
        *(uint4*)(g_Qt + obase + (size_t)(n0 + sn) * HDIM + h0 + shb) = *(uint4*)o;
    }
    __syncthreads();

    // ---- K + PE ----
#pragma unroll
    for (int i = 0; i < 2; i++) {
        const int idx = i * 512 + tid, row = idx >> 4, c4 = (idx & 15) * 4;
        const size_t g = ibase + (size_t)(h0 + row) * NDIM + n0 + c4;
        const float4 kv = *(const float4*)(K + g);
        const float4 pv = *(const float4*)(PE + g);
        t[row][c4]     = kv.x + pv.x;
        t[row][c4 + 1] = kv.y + pv.y;
        t[row][c4 + 2] = kv.z + pv.z;
        t[row][c4 + 3] = kv.w + pv.w;
    }
    __syncthreads();
    {
        __align__(16) __half2 o[4];
#pragma unroll
        for (int j = 0; j < 4; j++)
            o[j] = __floats2half2_rn(t[shb + 2 * j][sn], t[shb + 2 * j + 1][sn]);
        *(uint4*)(g_Kt + obase + (size_t)(n0 + sn) * HDIM + h0 + shb) = *(uint4*)o;
    }
}

// Pre-pass 2: V -> fp16
__global__ __launch_bounds__(256)
void conv_v(const float* __restrict__ V) {
    const size_t i = ((size_t)blockIdx.x * 256 + threadIdx.x) * 8;
    const float4 v0 = *(const float4*)(V + i);
    const float4 v1 = *(const float4*)(V + i + 4);
    __align__(16) __half2 o[4];
    o[0] = __floats2half2_rn(v0.x, v0.y);
    o[1] = __floats2half2_rn(v0.z, v0.w);
    o[2] = __floats2half2_rn(v1.x, v1.y);
    o[3] = __floats2half2_rn(v1.z, v1.w);
    *(uint4*)(g_Vh + i) = *(uint4*)o;
}

// ===========================================================================
// Warp tile 64(A-rows) x 32(B-rows). Per chunk (KC=64): 4 ks iterations of
// 4 LDSM.x4 (A) + 2 LDSM.x4 (B) + 16 HMMA. acc[4][4][4] = 64 regs.
// ===========================================================================
__device__ __forceinline__ void mma_chunk(float acc[4][4][4], uint32_t stA, uint32_t stB,
                                          int wa, int wb, int lane) {
    const uint32_t aoff = stA + ((uint32_t)(wa + (lane & 15)) * PITCH + ((lane >> 4) * 8)) * 2;
    const uint32_t boff = stB + ((uint32_t)(wb + ((lane & 7) | ((lane & 16) >> 1))) * PITCH
                                 + (((lane >> 3) & 1) * 8)) * 2;
#pragma unroll
    for (int ks = 0; ks < 4; ks++) {
        uint32_t a[4][4], bb[4][2];
        const uint32_t kb = ks * 32;   // 16 halfs = 32 bytes per ks
#pragma unroll
        for (int mf = 0; mf < 4; mf++)
            LDSM_X4(a[mf][0], a[mf][1], a[mf][2], a[mf][3],
                    aoff + kb + mf * (16 * PITCH * 2));
#pragma unroll
        for (int n2 = 0; n2 < 2; n2++)
            LDSM_X4(bb[2 * n2][0], bb[2 * n2][1], bb[2 * n2 + 1][0], bb[2 * n2 + 1][1],
                    boff + kb + n2 * (16 * PITCH * 2));
#pragma unroll
        for (int mf = 0; mf < 4; mf++)
#pragma unroll
            for (int nf = 0; nf < 4; nf++)
                mma_f16(acc[mf][nf], a[mf], bb[nf]);
    }
}

// ===========================================================================
// GEMM1: S[n][m] = sum_h Qt[n][h]*Kt[m][h]. CTA 128(n) x 128(m), 8 warps as
// 2(n) x 4(m), warp tile 64x32. 3-stage cp.async pipeline, KC=64. 2 CTAs/SM.
// ===========================================================================
__global__ __launch_bounds__(NTHREADS, 2)
void gemm1_k() {
    extern __shared__ __half S[];
    const int b = blockIdx.z, m0 = blockIdx.x * 128, n0 = blockIdx.y * 128;
    const int tid = threadIdx.x, lane = tid & 31, w = tid >> 5;
    const int gid = lane >> 2, tig = lane & 3;
    const int wn = (w & 1) * 64;    // n offset (A rows)
    const int wm = (w >> 1) * 32;   // m offset (B rows)

    const __half* Qb = g_Qt + (size_t)b * NDIM * HDIM + (size_t)n0 * HDIM;
    const __half* Kb = g_Kt + (size_t)b * NDIM * HDIM + (size_t)m0 * HDIM;
    const uint32_t sbase = smem_u32(S);

    float acc[4][4][4];
#pragma unroll
    for (int i = 0; i < 4; i++)
#pragma unroll
        for (int j = 0; j < 4; j++)
#pragma unroll
            for (int r = 0; r < 4; r++) acc[i][j][r] = 0.f;

    auto fill = [&](int c, int stg) {
        const int hc = c * KC;
        const uint32_t dA = sbase + stg * STAGE * 2;
        const uint32_t dB = dA + STAGE_A * 2;
#pragma unroll
        for (int i = 0; i < 4; i++) {   // A: 128 rows x 8 units = 1024 ops
            const int idx = i * NTHREADS + tid, row = idx >> 3, u = idx & 7;
            cpa16(dA + (row * PITCH + u * 8) * 2, Qb + (size_t)row * HDIM + hc + u * 8);
        }
#pragma unroll
        for (int i = 0; i < 4; i++) {   // B: 128 rows x 8 units = 1024 ops
            const int idx = i * NTHREADS + tid, row = idx >> 3, u = idx & 7;
            cpa16(dB + (row * PITCH + u * 8) * 2, Kb + (size_t)row * HDIM + hc + u * 8);
        }
        CP_COMMIT();
    };

    const int NC = HDIM / KC;   // 12
    fill(0, 0); fill(1, 1);
    int stg = 0;
#pragma unroll 1
    for (int c = 0; c < NC; c++) {
        CP_WAIT1();
        __syncthreads();
        if (c + 2 < NC) {
            int s2 = stg + 2; if (s2 >= NSTAGE) s2 -= NSTAGE;
            fill(c + 2, s2);
        } else CP_COMMIT();
        const uint32_t stA = sbase + stg * STAGE * 2;
        mma_chunk(acc, stA, stA + STAGE_A * 2, wn, wm, lane);
        if (++stg == NSTAGE) stg = 0;
    }
    __syncthreads();

    // Epilogue: round to fp16, store E, rowsum of rounded values.
    const float scale = 0.03608439182435161f;   // 1/sqrt(768)
    __half* Eb = g_Eh + (size_t)b * NDIM * NDIM;
    float* Lred = (float*)(S + NSTAGE * STAGE);      // [4][128]
#pragma unroll
    for (int mf = 0; mf < 4; mf++) {
        float rs0 = 0.f, rs1 = 0.f;
#pragma unroll
        for (int nf = 0; nf < 4; nf++) {
            __half2 h01 = __floats2half2_rn(__expf(acc[mf][nf][0] * scale),
                                            __expf(acc[mf][nf][1] * scale));
            __half2 h23 = __floats2half2_rn(__expf(acc[mf][nf][2] * scale),
                                            __expf(acc[mf][nf][3] * scale));
            float2 f01 = __half22float2(h01);
            float2 f23 = __half22float2(h23);
            rs0 += f01.x + f01.y;
            rs1 += f23.x + f23.y;
            const int row = n0 + wn + mf * 16 + gid;
            const int col = m0 + wm + nf * 8 + tig * 2;
            *(__half2*)(Eb + (size_t)row * NDIM + col)       = h01;
            *(__half2*)(Eb + (size_t)(row + 8) * NDIM + col) = h23;
        }
        rs0 += __shfl_xor_sync(0xffffffffu, rs0, 1);
        rs0 += __shfl_xor_sync(0xffffffffu, rs0, 2);
        rs1 += __shfl_xor_sync(0xffffffffu, rs1, 1);
        rs1 += __shfl_xor_sync(0xffffffffu, rs1, 2);
        if (tig == 0) {
            Lred[(w >> 1) * 128 + wn + mf * 16 + gid]     = rs0;
            Lred[(w >> 1) * 128 + wn + mf * 16 + gid + 8] = rs1;
        }
    }
    __syncthreads();
    if (tid < 128) {
        float s = 0.f;
#pragma unroll
        for (int j = 0; j < 4; j++) s += Lred[j * 128 + tid];
        g_Lpart[((size_t)b * 16 + blockIdx.x) * NDIM + n0 + tid] = s;
    }
}

// ===========================================================================
__global__ void rowsum_k() {
    const int t = blockIdx.x * blockDim.x + threadIdx.x;
    const int b = t >> 11, n = t & 2047;
    float s = 0.f;
#pragma unroll
    for (int j = 0; j < 16; j++)
        s += g_Lpart[((size_t)b * 16 + j) * NDIM + n];
    g_L[(size_t)b * NDIM + n] = 1.0f / s;
}

// ===========================================================================
// GEMM2: O[h][n] = (sum_m Vh[h][m]*Eh[n][m]) * Linv[n]. CTA 128(h) x 128(n),
// 8 warps as 2(h) x 4(n), warp tile 64x32. 3-stage pipeline, KC=64. 2 CTAs/SM.
// ===========================================================================
__global__ __launch_bounds__(NTHREADS, 2)
void gemm2_k(float* __restrict__ out) {
    extern __shared__ __half S[];
    const int b = blockIdx.z, n0 = blockIdx.x * 128, h0 = blockIdx.y * 128;
    const int tid = threadIdx.x, lane = tid & 31, w = tid >> 5;
    const int gid = lane >> 2, tig = lane & 3;
    const int wh = (w & 1) * 64;    // h offset (A rows)
    const int wn = (w >> 1) * 32;   // n offset (B rows)

    const __half* Vb = g_Vh + (size_t)b * HDIM * NDIM + (size_t)h0 * NDIM;
    const __half* Eb = g_Eh + (size_t)b * NDIM * NDIM + (size_t)n0 * NDIM;
    const uint32_t sbase = smem_u32(S);

    float acc[4][4][4];
#pragma unroll
    for (int i = 0; i < 4; i++)
#pragma unroll
        for (int j = 0; j < 4; j++)
#pragma unroll
            for (int r = 0; r < 4; r++) acc[i][j][r] = 0.f;

    auto fill = [&](int c, int stg) {
        const int mc = c * KC;
        const uint32_t dA = sbase + stg * STAGE * 2;
        const uint32_t dB = dA + STAGE_A * 2;
#pragma unroll
        for (int i = 0; i < 4; i++) {
            const int idx = i * NTHREADS + tid, row = idx >> 3, u = idx & 7;
            cpa16(dA + (row * PITCH + u * 8) * 2, Vb + (size_t)row * NDIM + mc + u * 8);
        }
#pragma unroll
        for (int i = 0; i < 4; i++) {
            const int idx = i * NTHREADS + tid, row = idx >> 3, u = idx & 7;
            cpa16(dB + (row * PITCH + u * 8) * 2, Eb + (size_t)row * NDIM + mc + u * 8);
        }
        CP_COMMIT();
    };

    const int NC = NDIM / KC;   // 32
    fill(0, 0); fill(1, 1);
    int stg = 0;
#pragma unroll 1
    for (int c = 0; c < NC; c++) {
        CP_WAIT1();
        __syncthreads();
        if (c + 2 < NC) {
            int s2 = stg + 2; if (s2 >= NSTAGE) s2 -= NSTAGE;
            fill(c + 2, s2);
        } else CP_COMMIT();
        const uint32_t stA = sbase + stg * STAGE * 2;
        mma_chunk(acc, stA, stA + STAGE_A * 2, wh, wn, lane);
        if (++stg == NSTAGE) stg = 0;
    }

    // Epilogue: multiply by 1/L[n], store fp32
    const float* Li = g_L + (size_t)b * NDIM;
#pragma unroll
    for (int nf = 0; nf < 4; nf++) {
        const int col = n0 + wn + nf * 8 + tig * 2;
        const float iv0 = Li[col], iv1 = Li[col + 1];
#pragma unroll
        for (int mf = 0; mf < 4; mf++) {
            const int row = h0 + wh + mf * 16 + gid;
            *(float2*)(out + (size_t)(b * HDIM + row) * NDIM + col) =
                make_float2(acc[mf][nf][0] * iv0, acc[mf][nf][1] * iv1);
            *(float2*)(out + (size_t)(b * HDIM + row + 8) * NDIM + col) =
                make_float2(acc[mf][nf][2] * iv0, acc[mf][nf][3] * iv1);
        }
    }
}

// ===========================================================================
extern "C" void kernel_launch(void* const* d_in, const int* in_sizes, int n_in,
                              void* d_out, int out_size) {
    const float* q  = (const float*)d_in[0];
    const float* k  = (const float*)d_in[1];
    const float* v  = (const float*)d_in[2];
    const float* pe = (const float*)d_in[3];
    float* out = (float*)d_out;

    cudaFuncSetAttribute(gemm1_k, cudaFuncAttributeMaxDynamicSharedMemorySize, SMEM_BYTES);
    cudaFuncSetAttribute(gemm2_k, cudaFuncAttributeMaxDynamicSharedMemorySize, SMEM_BYTES);

    prep_qk<<<dim3(NDIM / 64, HDIM / 64, BATCH), 512>>>(q, k, pe);
    conv_v<<<(BATCH * HDIM * NDIM) / 2048, 256>>>(v);
    gemm1_k<<<dim3(16, 16, BATCH), NTHREADS, SMEM_BYTES>>>();
    rowsum_k<<<(BATCH * NDIM) / 256, 256>>>();
    gemm2_k<<<dim3(16, 6, BATCH), NTHREADS, SMEM_BYTES>>>(out);
}

// round 15
// speedup vs baseline: 2.8972x; 1.0996x over previous
#include <cuda_runtime.h>
#include <cuda_fp16.h>
#include <math.h>
#include <stdint.h>

#define BATCH 16
#define HDIM  768
#define NDIM  2048
#define KC    64            // k elements per chunk (fp16)
#define PITCH 72            // smem row pitch in halfs (144B, LDSM/cp.async conflict-free)
#define STAGE_A (128 * PITCH)
#define STAGE_B (128 * PITCH)
#define STAGE   (STAGE_A + STAGE_B)          // halfs per stage (18432 = 36864B)
#define NSTAGE  3
#define NTHREADS 256
#define MBAR_OFF (NSTAGE * STAGE * 2 + 2048) // after stages + Lred
#define SMEM_BYTES (MBAR_OFF + 64)           // + 6 mbarriers

// Scratch (allocation-free rule: __device__ globals)
__device__ __half g_Qt[(size_t)BATCH * NDIM * HDIM];  // [b][n][h]
__device__ __half g_Kt[(size_t)BATCH * NDIM * HDIM];  // [b][m][h] = fp16(K+PE)
__device__ __half g_Vh[(size_t)BATCH * HDIM * NDIM];  // [b][h][m]
__device__ __half g_Eh[(size_t)BATCH * NDIM * NDIM];  // [b][n][m] exp(logits)
__device__ float  g_Lpart[(size_t)BATCH * 16 * NDIM];
__device__ float  g_L[(size_t)BATCH * NDIM];          // 1 / rowsum

__device__ __forceinline__ uint32_t smem_u32(const void* p) {
    uint32_t a;
    asm("{ .reg .u64 t; cvta.to.shared.u64 t, %1; cvt.u32.u64 %0, t; }" : "=r"(a) : "l"(p));
    return a;
}
__device__ __forceinline__ void cpa16(uint32_t dst, const void* src) {
    asm volatile("cp.async.cg.shared.global [%0], [%1], 16;" :: "r"(dst), "l"(src));
}

// ---- mbarrier ring machinery ----
#define MBAR_INIT(a, n) \
    asm volatile("mbarrier.init.shared.b64 [%0], %1;" :: "r"(a), "r"((unsigned)(n)) : "memory")
#define MBAR_ARRIVE(a) \
    asm volatile("{\n\t.reg .b64 t;\n\tmbarrier.arrive.shared.b64 t, [%0];\n\t}" \
                 :: "r"(a) : "memory")
#define CP_MBAR_ARRIVE(a) \
    asm volatile("cp.async.mbarrier.arrive.noinc.shared.b64 [%0];" :: "r"(a) : "memory")
#define MBAR_WAIT(a, p) \
    asm volatile("{\n\t.reg .pred P;\n\tLAB%=:\n\t" \
                 "mbarrier.try_wait.parity.acquire.cta.shared::cta.b64 P, [%0], %1, 0x989680;\n\t" \
                 "@!P bra LAB%=;\n\t}" :: "r"(a), "r"((unsigned)(p)) : "memory")

#define LDSM_X4(r0, r1, r2, r3, addr) \
    asm volatile("ldmatrix.sync.aligned.m8n8.x4.shared.b16 {%0,%1,%2,%3}, [%4];" \
                 : "=r"(r0), "=r"(r1), "=r"(r2), "=r"(r3) : "r"(addr))

__device__ __forceinline__ void mma_f16(float* c, const uint32_t* a, const uint32_t* b) {
    asm volatile(
        "mma.sync.aligned.m16n8k16.row.col.f32.f16.f16.f32 "
        "{%0,%1,%2,%3}, {%4,%5,%6,%7}, {%8,%9}, {%0,%1,%2,%3};\n"
        : "+f"(c[0]), "+f"(c[1]), "+f"(c[2]), "+f"(c[3])
        : "r"(a[0]), "r"(a[1]), "r"(a[2]), "r"(a[3]), "r"(b[0]), "r"(b[1]));
}

// ===========================================================================
// Pre-pass 1: transpose+convert, 64x64 tiles.
// ===========================================================================
__global__ __launch_bounds__(512)
void prep_qk(const float* __restrict__ Q, const float* __restrict__ K,
             const float* __restrict__ PE) {
    __shared__ float t[64][65];
    const int b = blockIdx.z, h0 = blockIdx.y * 64, n0 = blockIdx.x * 64;
    const int tid = threadIdx.x;
    const size_t ibase = (size_t)b * HDIM * NDIM;
    const size_t obase = (size_t)b * NDIM * HDIM;

    const int sn = tid >> 3, shb = (tid & 7) * 8;

    // ---- Q ----
#pragma unroll
    for (int i = 0; i < 2; i++) {
        const int idx = i * 512 + tid, row = idx >> 4, c4 = (idx & 15) * 4;
        const float4 v = *(const float4*)(Q + ibase + (size_t)(h0 + row) * NDIM + n0 + c4);
        t[row][c4] = v.x; t[row][c4 + 1] = v.y; t[row][c4 + 2] = v.z; t[row][c4 + 3] = v.w;
    }
    __syncthreads();
    {
        __align__(16) __half2 o[4];
#pragma unroll
        for (int j = 0; j < 4; j++)
            o[j] = __floats2half2_rn(t[shb + 2 * j][sn], t[shb + 2 * j + 1][sn]);
        *(uint4*)(g_Qt + obase + (size_t)(n0 + sn) * HDIM + h0 + shb) = *(uint4*)o;
    }
    __syncthreads();

    // ---- K + PE ----
#pragma unroll
    for (int i = 0; i < 2; i++) {
        const int idx = i * 512 + tid, row = idx >> 4, c4 = (idx & 15) * 4;
        const size_t g = ibase + (size_t)(h0 + row) * NDIM + n0 + c4;
        const float4 kv = *(const float4*)(K + g);
        const float4 pv = *(const float4*)(PE + g);
        t[row][c4]     = kv.x + pv.x;
        t[row][c4 + 1] = kv.y + pv.y;
        t[row][c4 + 2] = kv.z + pv.z;
        t[row][c4 + 3] = kv.w + pv.w;
    }
    __syncthreads();
    {
        __align__(16) __half2 o[4];
#pragma unroll
        for (int j = 0; j < 4; j++)
            o[j] = __floats2half2_rn(t[shb + 2 * j][sn], t[shb + 2 * j + 1][sn]);
        *(uint4*)(g_Kt + obase + (size_t)(n0 + sn) * HDIM + h0 + shb) = *(uint4*)o;
    }
}

// Pre-pass 2: V -> fp16
__global__ __launch_bounds__(256)
void conv_v(const float* __restrict__ V) {
    const size_t i = ((size_t)blockIdx.x * 256 + threadIdx.x) * 8;
    const float4 v0 = *(const float4*)(V + i);
    const float4 v1 = *(const float4*)(V + i + 4);
    __align__(16) __half2 o[4];
    o[0] = __floats2half2_rn(v0.x, v0.y);
    o[1] = __floats2half2_rn(v0.z, v0.w);
    o[2] = __floats2half2_rn(v1.x, v1.y);
    o[3] = __floats2half2_rn(v1.z, v1.w);
    *(uint4*)(g_Vh + i) = *(uint4*)o;
}

// ===========================================================================
// Warp tile 64(A-rows) x 32(B-rows). Per chunk (KC=64): 4 ks iterations of
// 4 LDSM.x4 (A) + 2 LDSM.x4 (B) + 16 HMMA. acc[4][4][4] = 64 regs.
// ===========================================================================
__device__ __forceinline__ void mma_chunk(float acc[4][4][4], uint32_t stA, uint32_t stB,
                                          int wa, int wb, int lane) {
    const uint32_t aoff = stA + ((uint32_t)(wa + (lane & 15)) * PITCH + ((lane >> 4) * 8)) * 2;
    const uint32_t boff = stB + ((uint32_t)(wb + ((lane & 7) | ((lane & 16) >> 1))) * PITCH
                                 + (((lane >> 3) & 1) * 8)) * 2;
#pragma unroll
    for (int ks = 0; ks < 4; ks++) {
        uint32_t a[4][4], bb[4][2];
        const uint32_t kb = ks * 32;   // 16 halfs = 32 bytes per ks
#pragma unroll
        for (int mf = 0; mf < 4; mf++)
            LDSM_X4(a[mf][0], a[mf][1], a[mf][2], a[mf][3],
                    aoff + kb + mf * (16 * PITCH * 2));
#pragma unroll
        for (int n2 = 0; n2 < 2; n2++)
            LDSM_X4(bb[2 * n2][0], bb[2 * n2][1], bb[2 * n2 + 1][0], bb[2 * n2 + 1][1],
                    boff + kb + n2 * (16 * PITCH * 2));
#pragma unroll
        for (int mf = 0; mf < 4; mf++)
#pragma unroll
            for (int nf = 0; nf < 4; nf++)
                mma_f16(acc[mf][nf], a[mf], bb[nf]);
    }
}

// ===========================================================================
// GEMM1: S[n][m] = sum_h Qt[n][h]*Kt[m][h]. CTA 128(n) x 128(m), 8 warps as
// 2(n) x 4(m), warp tile 64x32. mbarrier ring (S=3, F=2), KC=64. 2 CTAs/SM.
// ===========================================================================
__global__ __launch_bounds__(NTHREADS, 2)
void gemm1_k() {
    extern __shared__ __half S[];
    const int b = blockIdx.z, m0 = blockIdx.x * 128, n0 = blockIdx.y * 128;
    const int tid = threadIdx.x, lane = tid & 31, w = tid >> 5;
    const int gid = lane >> 2, tig = lane & 3;
    const int wn = (w & 1) * 64;    // n offset (A rows)
    const int wm = (w >> 1) * 32;   // m offset (B rows)

    const __half* Qb = g_Qt + (size_t)b * NDIM * HDIM + (size_t)n0 * HDIM;
    const __half* Kb = g_Kt + (size_t)b * NDIM * HDIM + (size_t)m0 * HDIM;
    const uint32_t sbase = smem_u32(S);
    const uint32_t mbF = sbase + MBAR_OFF;        // full[0..2]
    const uint32_t mbE = mbF + 24;                // empty[0..2]

    if (tid == 0) {
#pragma unroll
        for (int s = 0; s < NSTAGE; s++) {
            MBAR_INIT(mbF + s * 8, NTHREADS);
            MBAR_INIT(mbE + s * 8, NTHREADS);
        }
    }
    __syncthreads();

    float acc[4][4][4];
#pragma unroll
    for (int i = 0; i < 4; i++)
#pragma unroll
        for (int j = 0; j < 4; j++)
#pragma unroll
            for (int r = 0; r < 4; r++) acc[i][j][r] = 0.f;

    auto fill = [&](int f) {
        const int s = f % NSTAGE;
        if (f >= NSTAGE) MBAR_WAIT(mbE + s * 8, ((f / NSTAGE) - 1) & 1);
        const int hc = f * KC;
        const uint32_t dA = sbase + s * STAGE * 2;
        const uint32_t dB = dA + STAGE_A * 2;
#pragma unroll
        for (int i = 0; i < 4; i++) {
            const int idx = i * NTHREADS + tid, row = idx >> 3, u = idx & 7;
            cpa16(dA + (row * PITCH + u * 8) * 2, Qb + (size_t)row * HDIM + hc + u * 8);
        }
#pragma unroll
        for (int i = 0; i < 4; i++) {
            const int idx = i * NTHREADS + tid, row = idx >> 3, u = idx & 7;
            cpa16(dB + (row * PITCH + u * 8) * 2, Kb + (size_t)row * HDIM + hc + u * 8);
        }
        CP_MBAR_ARRIVE(mbF + s * 8);
    };

    const int NC = HDIM / KC;   // 12
    fill(0); fill(1);
#pragma unroll 1
    for (int c = 0; c < NC; c++) {
        if (c + 2 < NC) fill(c + 2);
        const int s = c % NSTAGE;
        MBAR_WAIT(mbF + s * 8, (c / NSTAGE) & 1);
        const uint32_t stA = sbase + s * STAGE * 2;
        mma_chunk(acc, stA, stA + STAGE_A * 2, wn, wm, lane);
        MBAR_ARRIVE(mbE + s * 8);
    }
    __syncthreads();

    // Epilogue: round to fp16, store E, rowsum of rounded values.
    const float scale = 0.03608439182435161f;   // 1/sqrt(768)
    __half* Eb = g_Eh + (size_t)b * NDIM * NDIM;
    float* Lred = (float*)(S + NSTAGE * STAGE);      // [4][128]
#pragma unroll
    for (int mf = 0; mf < 4; mf++) {
        float rs0 = 0.f, rs1 = 0.f;
#pragma unroll
        for (int nf = 0; nf < 4; nf++) {
            __half2 h01 = __floats2half2_rn(__expf(acc[mf][nf][0] * scale),
                                            __expf(acc[mf][nf][1] * scale));
            __half2 h23 = __floats2half2_rn(__expf(acc[mf][nf][2] * scale),
                                            __expf(acc[mf][nf][3] * scale));
            float2 f01 = __half22float2(h01);
            float2 f23 = __half22float2(h23);
            rs0 += f01.x + f01.y;
            rs1 += f23.x + f23.y;
            const int row = n0 + wn + mf * 16 + gid;
            const int col = m0 + wm + nf * 8 + tig * 2;
            *(__half2*)(Eb + (size_t)row * NDIM + col)       = h01;
            *(__half2*)(Eb + (size_t)(row + 8) * NDIM + col) = h23;
        }
        rs0 += __shfl_xor_sync(0xffffffffu, rs0, 1);
        rs0 += __shfl_xor_sync(0xffffffffu, rs0, 2);
        rs1 += __shfl_xor_sync(0xffffffffu, rs1, 1);
        rs1 += __shfl_xor_sync(0xffffffffu, rs1, 2);
        if (tig == 0) {
            Lred[(w >> 1) * 128 + wn + mf * 16 + gid]     = rs0;
            Lred[(w >> 1) * 128 + wn + mf * 16 + gid + 8] = rs1;
        }
    }
    __syncthreads();
    if (tid < 128) {
        float s = 0.f;
#pragma unroll
        for (int j = 0; j < 4; j++) s += Lred[j * 128 + tid];
        g_Lpart[((size_t)b * 16 + blockIdx.x) * NDIM + n0 + tid] = s;
    }
}

// ===========================================================================
__global__ void rowsum_k() {
    const int t = blockIdx.x * blockDim.x + threadIdx.x;
    const int b = t >> 11, n = t & 2047;
    float s = 0.f;
#pragma unroll
    for (int j = 0; j < 16; j++)
        s += g_Lpart[((size_t)b * 16 + j) * NDIM + n];
    g_L[(size_t)b * NDIM + n] = 1.0f / s;
}

// ===========================================================================
// GEMM2: O[h][n] = (sum_m Vh[h][m]*Eh[n][m]) * Linv[n]. CTA 128(h) x 128(n),
// 8 warps as 2(h) x 4(n), warp tile 64x32. mbarrier ring, KC=64. 2 CTAs/SM.
// ===========================================================================
__global__ __launch_bounds__(NTHREADS, 2)
void gemm2_k(float* __restrict__ out) {
    extern __shared__ __half S[];
    const int b = blockIdx.z, n0 = blockIdx.x * 128, h0 = blockIdx.y * 128;
    const int tid = threadIdx.x, lane = tid & 31, w = tid >> 5;
    const int gid = lane >> 2, tig = lane & 3;
    const int wh = (w & 1) * 64;    // h offset (A rows)
    const int wn = (w >> 1) * 32;   // n offset (B rows)

    const __half* Vb = g_Vh + (size_t)b * HDIM * NDIM + (size_t)h0 * NDIM;
    const __half* Eb = g_Eh + (size_t)b * NDIM * NDIM + (size_t)n0 * NDIM;
    const uint32_t sbase = smem_u32(S);
    const uint32_t mbF = sbase + MBAR_OFF;
    const uint32_t mbE = mbF + 24;

    if (tid == 0) {
#pragma unroll
        for (int s = 0; s < NSTAGE; s++) {
            MBAR_INIT(mbF + s * 8, NTHREADS);
            MBAR_INIT(mbE + s * 8, NTHREADS);
        }
    }
    __syncthreads();

    float acc[4][4][4];
#pragma unroll
    for (int i = 0; i < 4; i++)
#pragma unroll
        for (int j = 0; j < 4; j++)
#pragma unroll
            for (int r = 0; r < 4; r++) acc[i][j][r] = 0.f;

    auto fill = [&](int f) {
        const int s = f % NSTAGE;
        if (f >= NSTAGE) MBAR_WAIT(mbE + s * 8, ((f / NSTAGE) - 1) & 1);
        const int mc = f * KC;
        const uint32_t dA = sbase + s * STAGE * 2;
        const uint32_t dB = dA + STAGE_A * 2;
#pragma unroll
        for (int i = 0; i < 4; i++) {
            const int idx = i * NTHREADS + tid, row = idx >> 3, u = idx & 7;
            cpa16(dA + (row * PITCH + u * 8) * 2, Vb + (size_t)row * NDIM + mc + u * 8);
        }
#pragma unroll
        for (int i = 0; i < 4; i++) {
            const int idx = i * NTHREADS + tid, row = idx >> 3, u = idx & 7;
            cpa16(dB + (row * PITCH + u * 8) * 2, Eb + (size_t)row * NDIM + mc + u * 8);
        }
        CP_MBAR_ARRIVE(mbF + s * 8);
    };

    const int NC = NDIM / KC;   // 32
    fill(0); fill(1);
#pragma unroll 1
    for (int c = 0; c < NC; c++) {
        if (c + 2 < NC) fill(c + 2);
        const int s = c % NSTAGE;
        MBAR_WAIT(mbF + s * 8, (c / NSTAGE) & 1);
        const uint32_t stA = sbase + s * STAGE * 2;
        mma_chunk(acc, stA, stA + STAGE_A * 2, wh, wn, lane);
        MBAR_ARRIVE(mbE + s * 8);
    }

    // Epilogue: multiply by 1/L[n], store fp32
    const float* Li = g_L + (size_t)b * NDIM;
#pragma unroll
    for (int nf = 0; nf < 4; nf++) {
        const int col = n0 + wn + nf * 8 + tig * 2;
        const float iv0 = Li[col], iv1 = Li[col + 1];
#pragma unroll
        for (int mf = 0; mf < 4; mf++) {
            const int row = h0 + wh + mf * 16 + gid;
            *(float2*)(out + (size_t)(b * HDIM + row) * NDIM + col) =
                make_float2(acc[mf][nf][0] * iv0, acc[mf][nf][1] * iv1);
            *(float2*)(out + (size_t)(b * HDIM + row + 8) * NDIM + col) =
                make_float2(acc[mf][nf][2] * iv0, acc[mf][nf][3] * iv1);
        }
    }
}

// ===========================================================================
extern "C" void kernel_launch(void* const* d_in, const int* in_sizes, int n_in,
                              void* d_out, int out_size) {
    const float* q  = (const float*)d_in[0];
    const float* k  = (const float*)d_in[1];
    const float* v  = (const float*)d_in[2];
    const float* pe = (const float*)d_in[3];
    float* out = (float*)d_out;

    cudaFuncSetAttribute(gemm1_k, cudaFuncAttributeMaxDynamicSharedMemorySize, SMEM_BYTES);
    cudaFuncSetAttribute(gemm2_k, cudaFuncAttributeMaxDynamicSharedMemorySize, SMEM_BYTES);

    prep_qk<<<dim3(NDIM / 64, HDIM / 64, BATCH), 512>>>(q, k, pe);
    conv_v<<<(BATCH * HDIM * NDIM) / 2048, 256>>>(v);
    gemm1_k<<<dim3(16, 16, BATCH), NTHREADS, SMEM_BYTES>>>();
    rowsum_k<<<(BATCH * NDIM) / 256, 256>>>();
    gemm2_k<<<dim3(16, 6, BATCH), NTHREADS, SMEM_BYTES>>>(out);
}

// round 16
// speedup vs baseline: 3.0788x; 1.0627x over previous
#include <cuda_runtime.h>
#include <cuda_fp16.h>
#include <math.h>
#include <stdint.h>

#define BATCH 16
#define HDIM  768
#define NDIM  2048
#define KC    64            // k elements per chunk (fp16)
#define PITCH 72            // smem row pitch in halfs (144B, LDSM/cp.async conflict-free)
#define STAGE_A (128 * PITCH)
#define STAGE_B (128 * PITCH)
#define STAGE   (STAGE_A + STAGE_B)          // halfs per stage (18432 = 36864B)
#define NSTAGE  3
#define NTHREADS 256
#define NWARPS  8
#define MBAR_OFF (NSTAGE * STAGE * 2 + 2048) // after stages + Lred
#define SMEM_BYTES (MBAR_OFF + 64)           // + 6 mbarriers

// Scratch (allocation-free rule: __device__ globals)
__device__ __half g_Qt[(size_t)BATCH * NDIM * HDIM];  // [b][n][h]
__device__ __half g_Kt[(size_t)BATCH * NDIM * HDIM];  // [b][m][h] = fp16(K+PE)
__device__ __half g_Vh[(size_t)BATCH * HDIM * NDIM];  // [b][h][m]
__device__ __half g_Eh[(size_t)BATCH * NDIM * NDIM];  // [b][n][m] exp(logits)
__device__ float  g_Lpart[(size_t)BATCH * 16 * NDIM];
__device__ float  g_L[(size_t)BATCH * NDIM];          // 1 / rowsum

__device__ __forceinline__ uint32_t smem_u32(const void* p) {
    uint32_t a;
    asm("{ .reg .u64 t; cvta.to.shared.u64 t, %1; cvt.u32.u64 %0, t; }" : "=r"(a) : "l"(p));
    return a;
}
__device__ __forceinline__ void cpa16(uint32_t dst, const void* src) {
    asm volatile("cp.async.cg.shared.global [%0], [%1], 16;" :: "r"(dst), "l"(src));
}

// ---- mbarrier ring machinery ----
#define MBAR_INIT(a, n) \
    asm volatile("mbarrier.init.shared.b64 [%0], %1;" :: "r"(a), "r"((unsigned)(n)) : "memory")
#define MBAR_ARRIVE(a) \
    asm volatile("{\n\t.reg .b64 t;\n\tmbarrier.arrive.shared.b64 t, [%0];\n\t}" \
                 :: "r"(a) : "memory")
#define CP_MBAR_ARRIVE(a) \
    asm volatile("cp.async.mbarrier.arrive.noinc.shared.b64 [%0];" :: "r"(a) : "memory")
#define MBAR_WAIT(a, p) \
    asm volatile("{\n\t.reg .pred P;\n\tLAB%=:\n\t" \
                 "mbarrier.try_wait.parity.acquire.cta.shared::cta.b64 P, [%0], %1, 0x989680;\n\t" \
                 "@!P bra LAB%=;\n\t}" :: "r"(a), "r"((unsigned)(p)) : "memory")

#define LDSM_X4(r0, r1, r2, r3, addr) \
    asm volatile("ldmatrix.sync.aligned.m8n8.x4.shared.b16 {%0,%1,%2,%3}, [%4];" \
                 : "=r"(r0), "=r"(r1), "=r"(r2), "=r"(r3) : "r"(addr))

__device__ __forceinline__ void mma_f16(float* c, const uint32_t* a, const uint32_t* b) {
    asm volatile(
        "mma.sync.aligned.m16n8k16.row.col.f32.f16.f16.f32 "
        "{%0,%1,%2,%3}, {%4,%5,%6,%7}, {%8,%9}, {%0,%1,%2,%3};\n"
        : "+f"(c[0]), "+f"(c[1]), "+f"(c[2]), "+f"(c[3])
        : "r"(a[0]), "r"(a[1]), "r"(a[2]), "r"(a[3]), "r"(b[0]), "r"(b[1]));
}

// ===========================================================================
// Pre-pass 1: transpose+convert, 64x64 tiles.
// ===========================================================================
__global__ __launch_bounds__(512)
void prep_qk(const float* __restrict__ Q, const float* __restrict__ K,
             const float* __restrict__ PE) {
    __shared__ float t[64][65];
    const int b = blockIdx.z, h0 = blockIdx.y * 64, n0 = blockIdx.x * 64;
    const int tid = threadIdx.x;
    const size_t ibase = (size_t)b * HDIM * NDIM;
    const size_t obase = (size_t)b * NDIM * HDIM;

    const int sn = tid >> 3, shb = (tid & 7) * 8;

    // ---- Q ----
#pragma unroll
    for (int i = 0; i < 2; i++) {
        const int idx = i * 512 + tid, row = idx >> 4, c4 = (idx & 15) * 4;
        const float4 v = *(const float4*)(Q + ibase + (size_t)(h0 + row) * NDIM + n0 + c4);
        t[row][c4] = v.x; t[row][c4 + 1] = v.y; t[row][c4 + 2] = v.z; t[row][c4 + 3] = v.w;
    }
    __syncthreads();
    {
        __align__(16) __half2 o[4];
#pragma unroll
        for (int j = 0; j < 4; j++)
            o[j] = __floats2half2_rn(t[shb + 2 * j][sn], t[shb + 2 * j + 1][sn]);
        *(uint4*)(g_Qt + obase + (size_t)(n0 + sn) * HDIM + h0 + shb) = *(uint4*)o;
    }
    __syncthreads();

    // ---- K + PE ----
#pragma unroll
    for (int i = 0; i < 2; i++) {
        const int idx = i * 512 + tid, row = idx >> 4, c4 = (idx & 15) * 4;
        const size_t g = ibase + (size_t)(h0 + row) * NDIM + n0 + c4;
        const float4 kv = *(const float4*)(K + g);
        const float4 pv = *(const float4*)(PE + g);
        t[row][c4]     = kv.x + pv.x;
        t[row][c4 + 1] = kv.y + pv.y;
        t[row][c4 + 2] = kv.z + pv.z;
        t[row][c4 + 3] = kv.w + pv.w;
    }
    __syncthreads();
    {
        __align__(16) __half2 o[4];
#pragma unroll
        for (int j = 0; j < 4; j++)
            o[j] = __floats2half2_rn(t[shb + 2 * j][sn], t[shb + 2 * j + 1][sn]);
        *(uint4*)(g_Kt + obase + (size_t)(n0 + sn) * HDIM + h0 + shb) = *(uint4*)o;
    }
}

// Pre-pass 2: V -> fp16
__global__ __launch_bounds__(256)
void conv_v(const float* __restrict__ V) {
    const size_t i = ((size_t)blockIdx.x * 256 + threadIdx.x) * 8;
    const float4 v0 = *(const float4*)(V + i);
    const float4 v1 = *(const float4*)(V + i + 4);
    __align__(16) __half2 o[4];
    o[0] = __floats2half2_rn(v0.x, v0.y);
    o[1] = __floats2half2_rn(v0.z, v0.w);
    o[2] = __floats2half2_rn(v1.x, v1.y);
    o[3] = __floats2half2_rn(v1.z, v1.w);
    *(uint4*)(g_Vh + i) = *(uint4*)o;
}

// ===========================================================================
// Warp tile 64(A-rows) x 32(B-rows). Per chunk (KC=64): 4 ks iterations of
// 4 LDSM.x4 (A) + 2 LDSM.x4 (B) + 16 HMMA. acc[4][4][4] = 64 regs.
// ===========================================================================
__device__ __forceinline__ void mma_chunk(float acc[4][4][4], uint32_t stA, uint32_t stB,
                                          int wa, int wb, int lane) {
    const uint32_t aoff = stA + ((uint32_t)(wa + (lane & 15)) * PITCH + ((lane >> 4) * 8)) * 2;
    const uint32_t boff = stB + ((uint32_t)(wb + ((lane & 7) | ((lane & 16) >> 1))) * PITCH
                                 + (((lane >> 3) & 1) * 8)) * 2;
#pragma unroll
    for (int ks = 0; ks < 4; ks++) {
        uint32_t a[4][4], bb[4][2];
        const uint32_t kb = ks * 32;   // 16 halfs = 32 bytes per ks
#pragma unroll
        for (int mf = 0; mf < 4; mf++)
            LDSM_X4(a[mf][0], a[mf][1], a[mf][2], a[mf][3],
                    aoff + kb + mf * (16 * PITCH * 2));
#pragma unroll
        for (int n2 = 0; n2 < 2; n2++)
            LDSM_X4(bb[2 * n2][0], bb[2 * n2][1], bb[2 * n2 + 1][0], bb[2 * n2 + 1][1],
                    boff + kb + n2 * (16 * PITCH * 2));
#pragma unroll
        for (int mf = 0; mf < 4; mf++)
#pragma unroll
            for (int nf = 0; nf < 4; nf++)
                mma_f16(acc[mf][nf], a[mf], bb[nf]);
    }
}

// ===========================================================================
// GEMM1: S[n][m] = sum_h Qt[n][h]*Kt[m][h]. CTA 128(n) x 128(m), 8 warps as
// 2(n) x 4(m), warp tile 64x32. mbarrier ring (S=3, F=2), KC=64. 2 CTAs/SM.
// Loop order: wait full -> mma -> arrive empty (lane0) -> fill next.
// ===========================================================================
__global__ __launch_bounds__(NTHREADS, 2)
void gemm1_k() {
    extern __shared__ __half S[];
    const int b = blockIdx.z, m0 = blockIdx.x * 128, n0 = blockIdx.y * 128;
    const int tid = threadIdx.x, lane = tid & 31, w = tid >> 5;
    const int gid = lane >> 2, tig = lane & 3;
    const int wn = (w & 1) * 64;    // n offset (A rows)
    const int wm = (w >> 1) * 32;   // m offset (B rows)

    const __half* Qb = g_Qt + (size_t)b * NDIM * HDIM + (size_t)n0 * HDIM;
    const __half* Kb = g_Kt + (size_t)b * NDIM * HDIM + (size_t)m0 * HDIM;
    const uint32_t sbase = smem_u32(S);
    const uint32_t mbF = sbase + MBAR_OFF;        // full[0..2]
    const uint32_t mbE = mbF + 24;                // empty[0..2]

    if (tid == 0) {
#pragma unroll
        for (int s = 0; s < NSTAGE; s++) {
            MBAR_INIT(mbF + s * 8, NTHREADS);
            MBAR_INIT(mbE + s * 8, NWARPS);
        }
    }
    __syncthreads();

    float acc[4][4][4];
#pragma unroll
    for (int i = 0; i < 4; i++)
#pragma unroll
        for (int j = 0; j < 4; j++)
#pragma unroll
            for (int r = 0; r < 4; r++) acc[i][j][r] = 0.f;

    // fill chunk f into stage fs; ew = wait empty first (with parity ep)
    auto fill = [&](int f, int fs, int ew, int ep) {
        if (ew) MBAR_WAIT(mbE + fs * 8, ep);
        const int hc = f * KC;
        const uint32_t dA = sbase + fs * STAGE * 2;
        const uint32_t dB = dA + STAGE_A * 2;
#pragma unroll
        for (int i = 0; i < 4; i++) {
            const int idx = i * NTHREADS + tid, row = idx >> 3, u = idx & 7;
            cpa16(dA + (row * PITCH + u * 8) * 2, Qb + (size_t)row * HDIM + hc + u * 8);
        }
#pragma unroll
        for (int i = 0; i < 4; i++) {
            const int idx = i * NTHREADS + tid, row = idx >> 3, u = idx & 7;
            cpa16(dB + (row * PITCH + u * 8) * 2, Kb + (size_t)row * HDIM + hc + u * 8);
        }
        CP_MBAR_ARRIVE(mbF + fs * 8);
    };

    const int NC = HDIM / KC;   // 12
    fill(0, 0, 0, 0); fill(1, 1, 0, 0);
    int stg = 0, par = 0;          // stage/parity of chunk c
    int fstg = 2, fpar = 0;        // stage/parity of fill chunk c+2
    int festg = 2, fepar = 1;      // empty-wait parity helper: first wrap waits parity 0
#pragma unroll 1
    for (int c = 0; c < NC; c++) {
        MBAR_WAIT(mbF + stg * 8, par);
        const uint32_t stA = sbase + stg * STAGE * 2;
        mma_chunk(acc, stA, stA + STAGE_A * 2, wn, wm, lane);
        if (lane == 0) MBAR_ARRIVE(mbE + stg * 8);
        if (c + 2 < NC)
            fill(c + 2, fstg, (c + 2) >= NSTAGE, ((c + 2) / NSTAGE - 1) & 1);
        if (++stg == NSTAGE) { stg = 0; par ^= 1; }
        if (++fstg == NSTAGE) { fstg = 0; fpar ^= 1; }
    }
    __syncthreads();

    // Epilogue: round to fp16, store E, rowsum of rounded values.
    const float scale = 0.03608439182435161f;   // 1/sqrt(768)
    __half* Eb = g_Eh + (size_t)b * NDIM * NDIM;
    float* Lred = (float*)(S + NSTAGE * STAGE);      // [4][128]
#pragma unroll
    for (int mf = 0; mf < 4; mf++) {
        float rs0 = 0.f, rs1 = 0.f;
#pragma unroll
        for (int nf = 0; nf < 4; nf++) {
            __half2 h01 = __floats2half2_rn(__expf(acc[mf][nf][0] * scale),
                                            __expf(acc[mf][nf][1] * scale));
            __half2 h23 = __floats2half2_rn(__expf(acc[mf][nf][2] * scale),
                                            __expf(acc[mf][nf][3] * scale));
            float2 f01 = __half22float2(h01);
            float2 f23 = __half22float2(h23);
            rs0 += f01.x + f01.y;
            rs1 += f23.x + f23.y;
            const int row = n0 + wn + mf * 16 + gid;
            const int col = m0 + wm + nf * 8 + tig * 2;
            *(__half2*)(Eb + (size_t)row * NDIM + col)       = h01;
            *(__half2*)(Eb + (size_t)(row + 8) * NDIM + col) = h23;
        }
        rs0 += __shfl_xor_sync(0xffffffffu, rs0, 1);
        rs0 += __shfl_xor_sync(0xffffffffu, rs0, 2);
        rs1 += __shfl_xor_sync(0xffffffffu, rs1, 1);
        rs1 += __shfl_xor_sync(0xffffffffu, rs1, 2);
        if (tig == 0) {
            Lred[(w >> 1) * 128 + wn + mf * 16 + gid]     = rs0;
            Lred[(w >> 1) * 128 + wn + mf * 16 + gid + 8] = rs1;
        }
    }
    __syncthreads();
    if (tid < 128) {
        float s = 0.f;
#pragma unroll
        for (int j = 0; j < 4; j++) s += Lred[j * 128 + tid];
        g_Lpart[((size_t)b * 16 + blockIdx.x) * NDIM + n0 + tid] = s;
    }
}

// ===========================================================================
__global__ void rowsum_k() {
    const int t = blockIdx.x * blockDim.x + threadIdx.x;
    const int b = t >> 11, n = t & 2047;
    float s = 0.f;
#pragma unroll
    for (int j = 0; j < 16; j++)
        s += g_Lpart[((size_t)b * 16 + j) * NDIM + n];
    g_L[(size_t)b * NDIM + n] = 1.0f / s;
}

// ===========================================================================
// GEMM2: O[h][n] = (sum_m Vh[h][m]*Eh[n][m]) * Linv[n]. CTA 128(h) x 128(n),
// 8 warps as 2(h) x 4(n), warp tile 64x32. mbarrier ring, KC=64. 2 CTAs/SM.
// ===========================================================================
__global__ __launch_bounds__(NTHREADS, 2)
void gemm2_k(float* __restrict__ out) {
    extern __shared__ __half S[];
    const int b = blockIdx.z, n0 = blockIdx.x * 128, h0 = blockIdx.y * 128;
    const int tid = threadIdx.x, lane = tid & 31, w = tid >> 5;
    const int gid = lane >> 2, tig = lane & 3;
    const int wh = (w & 1) * 64;    // h offset (A rows)
    const int wn = (w >> 1) * 32;   // n offset (B rows)

    const __half* Vb = g_Vh + (size_t)b * HDIM * NDIM + (size_t)h0 * NDIM;
    const __half* Eb = g_Eh + (size_t)b * NDIM * NDIM + (size_t)n0 * NDIM;
    const uint32_t sbase = smem_u32(S);
    const uint32_t mbF = sbase + MBAR_OFF;
    const uint32_t mbE = mbF + 24;

    if (tid == 0) {
#pragma unroll
        for (int s = 0; s < NSTAGE; s++) {
            MBAR_INIT(mbF + s * 8, NTHREADS);
            MBAR_INIT(mbE + s * 8, NWARPS);
        }
    }
    __syncthreads();

    float acc[4][4][4];
#pragma unroll
    for (int i = 0; i < 4; i++)
#pragma unroll
        for (int j = 0; j < 4; j++)
#pragma unroll
            for (int r = 0; r < 4; r++) acc[i][j][r] = 0.f;

    auto fill = [&](int f, int fs, int ew, int ep) {
        if (ew) MBAR_WAIT(mbE + fs * 8, ep);
        const int mc = f * KC;
        const uint32_t dA = sbase + fs * STAGE * 2;
        const uint32_t dB = dA + STAGE_A * 2;
#pragma unroll
        for (int i = 0; i < 4; i++) {
            const int idx = i * NTHREADS + tid, row = idx >> 3, u = idx & 7;
            cpa16(dA + (row * PITCH + u * 8) * 2, Vb + (size_t)row * NDIM + mc + u * 8);
        }
#pragma unroll
        for (int i = 0; i < 4; i++) {
            const int idx = i * NTHREADS + tid, row = idx >> 3, u = idx & 7;
            cpa16(dB + (row * PITCH + u * 8) * 2, Eb + (size_t)row * NDIM + mc + u * 8);
        }
        CP_MBAR_ARRIVE(mbF + fs * 8);
    };

    const int NC = NDIM / KC;   // 32
    fill(0, 0, 0, 0); fill(1, 1, 0, 0);
    int stg = 0, par = 0;
    int fstg = 2;
#pragma unroll 1
    for (int c = 0; c < NC; c++) {
        MBAR_WAIT(mbF + stg * 8, par);
        const uint32_t stA = sbase + stg * STAGE * 2;
        mma_chunk(acc, stA, stA + STAGE_A * 2, wh, wn, lane);
        if (lane == 0) MBAR_ARRIVE(mbE + stg * 8);
        if (c + 2 < NC)
            fill(c + 2, fstg, (c + 2) >= NSTAGE, ((c + 2) / NSTAGE - 1) & 1);
        if (++stg == NSTAGE) { stg = 0; par ^= 1; }
        if (++fstg == NSTAGE) fstg = 0;
    }

    // Epilogue: multiply by 1/L[n], store fp32
    const float* Li = g_L + (size_t)b * NDIM;
#pragma unroll
    for (int nf = 0; nf < 4; nf++) {
        const int col = n0 + wn + nf * 8 + tig * 2;
        const float iv0 = Li[col], iv1 = Li[col + 1];
#pragma unroll
        for (int mf = 0; mf < 4; mf++) {
            const int row = h0 + wh + mf * 16 + gid;
            *(float2*)(out + (size_t)(b * HDIM + row) * NDIM + col) =
                make_float2(acc[mf][nf][0] * iv0, acc[mf][nf][1] * iv1);
            *(float2*)(out + (size_t)(b * HDIM + row + 8) * NDIM + col) =
                make_float2(acc[mf][nf][2] * iv0, acc[mf][nf][3] * iv1);
        }
    }
}

// ===========================================================================
extern "C" void kernel_launch(void* const* d_in, const int* in_sizes, int n_in,
                              void* d_out, int out_size) {
    const float* q  = (const float*)d_in[0];
    const float* k  = (const float*)d_in[1];
    const float* v  = (const float*)d_in[2];
    const float* pe = (const float*)d_in[3];
    float* out = (float*)d_out;

    cudaFuncSetAttribute(gemm1_k, cudaFuncAttributeMaxDynamicSharedMemorySize, SMEM_BYTES);
    cudaFuncSetAttribute(gemm2_k, cudaFuncAttributeMaxDynamicSharedMemorySize, SMEM_BYTES);

    prep_qk<<<dim3(NDIM / 64, HDIM / 64, BATCH), 512>>>(q, k, pe);
    conv_v<<<(BATCH * HDIM * NDIM) / 2048, 256>>>(v);
    gemm1_k<<<dim3(16, 16, BATCH), NTHREADS, SMEM_BYTES>>>();
    rowsum_k<<<(BATCH * NDIM) / 256, 256>>>();
    gemm2_k<<<dim3(16, 6, BATCH), NTHREADS, SMEM_BYTES>>>(out);
}